// round 10
// baseline (speedup 1.0000x reference)
#include <cuda_runtime.h>
#include <math.h>
#include <stdint.h>

#define Tdim 2048
#define Ddim 256
#define CACT 64
#define CTIME 32
#define NROWS (8 * 2048)
#define LABEL_ID_ 3
#define OBSTR 98
#define CHUNK 64

// dynamic smem layout (gemm role), byte offsets
#define B_HI 0                  // 256 x 208B  ([k][96n bf16 + 8 pad])
#define B_LO 53248
#define A_HI 106496             // 128 x 256B  (one K-half, swizzled)
#define A_LO 139264
#define SMEM_BYTES 172032

// proto smem layout (float offsets)
#define P_Q    0                // 32 x 256
#define P_HN   8192             // 64 x 260 (padded)
#define P_G    24832            // 64 x 64
#define P_M    28928            // 64 x 32
#define P_SB   30976            // 64 x 32
#define P_INT  33024            // ints from here: toks, ev_t, ev_n, ev_pc

__device__ float g_scr[(long)NROWS * 96];
__device__ int   g_done[8];

__device__ __forceinline__ float softplusf(float x) { return log1pf(expf(x)); }

__device__ __forceinline__ uint32_t smem_u32(const void* p) {
    uint32_t a;
    asm("{ .reg .u64 t; cvta.to.shared.u64 t, %1; cvt.u32.u64 %0, t; }" : "=r"(a) : "l"(p));
    return a;
}
__device__ __forceinline__ void hilo2(float x0, float x1, uint32_t& hi, uint32_t& lo) {
    asm("cvt.rn.bf16x2.f32 %0, %1, %2;" : "=r"(hi) : "f"(x1), "f"(x0));
    float h0 = __uint_as_float(hi << 16);
    float h1 = __uint_as_float(hi & 0xffff0000u);
    asm("cvt.rn.bf16x2.f32 %0, %1, %2;" : "=r"(lo) : "f"(x1 - h1), "f"(x0 - h0));
}
__device__ __forceinline__ void ldsm4(uint32_t addr, uint32_t& r0, uint32_t& r1,
                                      uint32_t& r2, uint32_t& r3) {
    asm volatile("ldmatrix.sync.aligned.m8n8.x4.shared.b16 {%0,%1,%2,%3}, [%4];"
                 : "=r"(r0), "=r"(r1), "=r"(r2), "=r"(r3) : "r"(addr));
}
__device__ __forceinline__ void ldsm4t(uint32_t addr, uint32_t& r0, uint32_t& r1,
                                       uint32_t& r2, uint32_t& r3) {
    asm volatile("ldmatrix.sync.aligned.m8n8.x4.trans.shared.b16 {%0,%1,%2,%3}, [%4];"
                 : "=r"(r0), "=r"(r1), "=r"(r2), "=r"(r3) : "r"(addr));
}
__device__ __forceinline__ void mma16816(float* c, uint32_t a0, uint32_t a1,
                                         uint32_t a2, uint32_t a3,
                                         uint32_t b0, uint32_t b1) {
    asm volatile(
        "mma.sync.aligned.m16n8k16.row.col.f32.bf16.bf16.f32 "
        "{%0,%1,%2,%3},{%4,%5,%6,%7},{%8,%9},{%0,%1,%2,%3};"
        : "+f"(c[0]), "+f"(c[1]), "+f"(c[2]), "+f"(c[3])
        : "r"(a0), "r"(a1), "r"(a2), "r"(a3), "r"(b0), "r"(b1));
}

__global__ void reset_kernel() {
    if (threadIdx.x < 8) g_done[threadIdx.x] = 0;
}

__global__ void __launch_bounds__(512, 1) fat_kernel(
    const int* __restrict__ tokens, const float* __restrict__ h,
    const float* __restrict__ E,
    const float* __restrict__ Wn, const float* __restrict__ bn,
    const float* __restrict__ Wt, const float* __restrict__ bt,
    const float* __restrict__ tsa, const float* __restrict__ tst,
    const float* __restrict__ psa, const float* __restrict__ pst,
    const float* __restrict__ ppa, const float* __restrict__ ppt,
    const float* __restrict__ pta, const float* __restrict__ ptt,
    float* __restrict__ out)
{
    extern __shared__ char smc[];
    float* sm = (float*)smc;
    int tid = threadIdx.x, lane = tid & 31, wid = tid >> 5;
    int bx = blockIdx.x;

    if (bx >= 24) {
        // =============== GEMM role: HMMA bf16 hi/lo split (unchanged from R9) ===============
        __shared__ float s_bias[96];
        __shared__ int s_lab[128];
        __shared__ int s_nlab;

        long rowbase = (long)(bx - 24) * 128;
        int b = (int)(rowbase >> 11);
        float s_ta = softplusf(*tsa), s_tt = softplusf(*tst);

        if (tid == 0) s_nlab = 0;
        if (tid < 96) s_bias[tid] = (tid < CACT) ? bn[tid] : bt[tid - CACT];

        uint32_t smem_base = smem_u32(smc);
        int rt = wid >> 1;
        int ch = wid & 1;

        float acc[6][4];
#pragma unroll
        for (int j = 0; j < 6; ++j)
#pragma unroll
            for (int i = 0; i < 4; ++i) acc[j][i] = 0.f;

        // stage B (folded weights, full K) as [k][n] hi/lo
        {
            const float2* E2 = (const float2*)E;
#pragma unroll
            for (int it = 0; it < 24; ++it) {
                int i = tid + 512 * it;
                int c = i >> 7, kp = i & 127;
                const float2* wrow = (const float2*)((c < CACT) ? (Wn + c * Ddim)
                                                                : (Wt + (c - CACT) * Ddim));
                int erow = (c < CACT) ? (4 + c) : (68 + (c - CACT));
                float sc = (c < CACT) ? s_ta : s_tt;
                float2 wv = wrow[kp];
                float2 ev = E2[erow * 128 + kp];
                float x0 = fmaf(sc, ev.x, wv.x), x1 = fmaf(sc, ev.y, wv.y);
                uint32_t hi, lo;
                hilo2(x0, x1, hi, lo);
                int k = 2 * kp;
                *(unsigned short*)(smc + B_HI + k * 208 + c * 2)       = (unsigned short)(hi & 0xffff);
                *(unsigned short*)(smc + B_HI + (k + 1) * 208 + c * 2) = (unsigned short)(hi >> 16);
                *(unsigned short*)(smc + B_LO + k * 208 + c * 2)       = (unsigned short)(lo & 0xffff);
                *(unsigned short*)(smc + B_LO + (k + 1) * 208 + c * 2) = (unsigned short)(lo >> 16);
            }
        }

        const float4* gh4 = (const float4*)h;
        int a_row = rt * 16 + (lane & 15);
        int a_half = lane >> 4;
        int b_kl = ((lane & 8) ? 8 : 0) + (lane & 7);
        int b_ntsel = (lane < 16) ? 0 : 1;

        for (int s = 0; s < 2; ++s) {
            __syncthreads();
#pragma unroll
            for (int it = 0; it < 4; ++it) {
                int i = tid + 512 * it;
                int r = i >> 4, c = i & 15;
                float4 v0 = gh4[(rowbase + r) * 64 + s * 32 + 2 * c];
                float4 v1 = gh4[(rowbase + r) * 64 + s * 32 + 2 * c + 1];
                uint4 hi4, lo4;
                hilo2(v0.x, v0.y, hi4.x, lo4.x);
                hilo2(v0.z, v0.w, hi4.y, lo4.y);
                hilo2(v1.x, v1.y, hi4.z, lo4.z);
                hilo2(v1.z, v1.w, hi4.w, lo4.w);
                int sw = (c ^ (r & 7)) * 16;
                *(uint4*)(smc + A_HI + r * 256 + sw) = hi4;
                *(uint4*)(smc + A_LO + r * 256 + sw) = lo4;
            }
            __syncthreads();

#pragma unroll
            for (int kc = 0; kc < 8; ++kc) {
                int chunk = kc * 2 + a_half;
                uint32_t a_off = a_row * 256 + ((chunk ^ (a_row & 7)) * 16);
                uint32_t aH0, aH1, aH2, aH3, aL0, aL1, aL2, aL3;
                ldsm4(smem_base + A_HI + a_off, aH0, aH1, aH2, aH3);
                ldsm4(smem_base + A_LO + a_off, aL0, aL1, aL2, aL3);

                int k0 = s * 128 + kc * 16;
                uint32_t bH[12], bL[12];
#pragma unroll
                for (int j2 = 0; j2 < 3; ++j2) {
                    int nof = ch * 48 + j2 * 16 + b_ntsel * 8;
                    uint32_t b_off = (k0 + b_kl) * 208 + nof * 2;
                    ldsm4t(smem_base + B_HI + b_off,
                           bH[4 * j2 + 0], bH[4 * j2 + 1], bH[4 * j2 + 2], bH[4 * j2 + 3]);
                    ldsm4t(smem_base + B_LO + b_off,
                           bL[4 * j2 + 0], bL[4 * j2 + 1], bL[4 * j2 + 2], bL[4 * j2 + 3]);
                }
#pragma unroll
                for (int j = 0; j < 6; ++j) {
                    mma16816(acc[j], aH0, aH1, aH2, aH3, bH[2 * j], bH[2 * j + 1]);
                    mma16816(acc[j], aH0, aH1, aH2, aH3, bL[2 * j], bL[2 * j + 1]);
                    mma16816(acc[j], aL0, aL1, aL2, aL3, bH[2 * j], bH[2 * j + 1]);
                }
            }
        }

        if (tid < 128) {
            int tok = tokens[rowbase + tid];
            if (tok == LABEL_ID_) {
                int idx = atomicAdd(&s_nlab, 1);
                s_lab[idx] = tid;
            }
        }

        __syncthreads();
        float* ob = sm;
        {
            int r0 = rt * 16 + (lane >> 2);
            int cb = ch * 48 + 2 * (lane & 3);
#pragma unroll
            for (int j = 0; j < 6; ++j) {
                int col = cb + 8 * j;
                float2 v0 = make_float2(acc[j][0] + s_bias[col], acc[j][1] + s_bias[col + 1]);
                float2 v1 = make_float2(acc[j][2] + s_bias[col], acc[j][3] + s_bias[col + 1]);
                *(float2*)(ob + r0 * OBSTR + col) = v0;
                *(float2*)(ob + (r0 + 8) * OBSTR + col) = v1;
            }
        }
        if (tid == 0) {
            while (*(volatile int*)&g_done[b] < 3) __nanosleep(64);
        }
        __syncthreads();
        int nlab = s_nlab;
        for (int i = 0; i < nlab; ++i) {
            int r = s_lab[i];
            if (tid < 96)
                ob[r * OBSTR + tid] += __ldcg(&g_scr[(rowbase + r) * 96 + tid]);
        }
        __syncthreads();

        float* outT = out + (long)NROWS * CACT;
#pragma unroll
        for (int k = 0; k < 8; ++k) {
            int i = tid + 512 * k;
            int r = i >> 5, c2 = i & 31;
            float2 v = *(float2*)(ob + r * OBSTR + 2 * c2);
            *(float2*)(out + (rowbase + r) * CACT + 2 * c2) = v;
        }
#pragma unroll
        for (int k = 0; k < 4; ++k) {
            int i = tid + 512 * k;
            int r = i >> 4, c2 = i & 15;
            float2 v = *(float2*)(ob + r * OBSTR + CACT + 2 * c2);
            *(float2*)(outT + (rowbase + r) * CTIME + 2 * c2) = v;
        }
    } else {
        // =============== proto role: batched G/M formulation ===============
        int b = bx / 3, part = bx % 3;
        int clo = (part == 0) ? 4 : (part == 1) ? 36 : 68;
        int klo = (part == 2) ? 68 : 4;
        int khi = (part == 2) ? 100 : 68;
        int cbase = part * 32;

        float* Q  = sm + P_Q;       // 32 x 256: q_c = alpha*En + carried support sums
        float* Hn = sm + P_HN;      // 64 x 260
        float* G  = sm + P_G;       // 64 x 64
        float* M  = sm + P_M;       // 64 x 32
        float* SB = sm + P_SB;      // 64 x 32 sims buffer
        int* toks  = (int*)(sm + P_INT);
        int* ev_t  = toks + Tdim;
        int* ev_n  = ev_t + Tdim;
        int* ev_pc = ev_n + Tdim;   // exclusive prefix count of kind-supports
        __shared__ int s_nev;
        __shared__ float s_n2[32];

        for (int i = tid; i < Tdim; i += 512) toks[i] = tokens[(long)b * Tdim + i];
        __syncthreads();

        if (wid == 0) {
            int cnt = 0;
            for (int ch2 = 0; ch2 < Tdim / 32; ++ch2) {
                int t = ch2 * 32 + lane;
                bool isl = (toks[t] == LABEL_ID_);
                unsigned m = __ballot_sync(0xffffffffu, isl);
                if (isl) {
                    int idx = cnt + __popc(m & ((1u << lane) - 1u));
                    ev_t[idx] = t;
                    ev_n[idx] = toks[(t + 1) & (Tdim - 1)];
                }
                cnt += __popc(m);
            }
            if (lane == 0) {
                s_nev = cnt;
                int run = 0;
                for (int e = 0; e < cnt; ++e) {
                    ev_pc[e] = run;
                    int nt = ev_n[e];
                    if (nt >= klo && nt < khi) run++;
                }
            }
        }

        float alpha = softplusf(part == 2 ? *ppt : *ppa);
        float scale = softplusf(part == 2 ? *pst : *psa) * softplusf(part == 2 ? *ptt : *pta);

        // Q init = alpha * l2norm(E[clo+c])
        for (int c = wid; c < 32; c += 16) {
            const float* e = E + (long)(clo + c) * Ddim;
            float v[8]; float ss = 0.f;
#pragma unroll
            for (int k = 0; k < 8; ++k) { v[k] = e[lane + 32 * k]; ss += v[k] * v[k]; }
#pragma unroll
            for (int o = 16; o > 0; o >>= 1) ss += __shfl_xor_sync(0xffffffffu, ss, o);
            float inv = alpha / fmaxf(sqrtf(ss), 1e-12f);
#pragma unroll
            for (int k = 0; k < 8; ++k) Q[c * Ddim + lane + 32 * k] = v[k] * inv;
        }
        if (tid < 32) s_n2[tid] = alpha * alpha;
        __syncthreads();

        int nev = s_nev;
        const float* hb = h + (long)b * Tdim * Ddim;

        for (int c0 = 0; c0 < nev; c0 += CHUNK) {
            int cl = min(CHUNK, nev - c0);

            // load + normalize chunk h rows (warp per row)
            for (int r = wid; r < cl; r += 16) {
                const float* hr = hb + (long)ev_t[c0 + r] * Ddim;
                float v[8]; float ss = 0.f;
#pragma unroll
                for (int k = 0; k < 8; ++k) { v[k] = hr[lane + 32 * k]; ss += v[k] * v[k]; }
#pragma unroll
                for (int o = 16; o > 0; o >>= 1) ss += __shfl_xor_sync(0xffffffffu, ss, o);
                float inv = 1.0f / fmaxf(sqrtf(ss), 1e-12f);
#pragma unroll
                for (int k = 0; k < 8; ++k) Hn[r * 260 + lane + 32 * k] = v[k] * inv;
            }
            __syncthreads();

            // G = Hn Hn^T  (cl x cl), M = Hn Q^T (cl x 32)
            int totG = cl * cl;
            for (int idx = tid; idx < totG; idx += 512) {
                int i = idx / cl, j = idx - i * cl;
                const float4* A = (const float4*)(Hn + i * 260);
                const float4* B4 = (const float4*)(Hn + j * 260);
                float s = 0.f;
#pragma unroll
                for (int k = 0; k < 64; ++k) {
                    float4 a = A[k], bb = B4[k];
                    s += a.x * bb.x + a.y * bb.y + a.z * bb.z + a.w * bb.w;
                }
                G[i * 64 + j] = s;
            }
            for (int idx = tid; idx < cl * 32; idx += 512) {
                int e = idx >> 5, c = idx & 31;
                const float4* A = (const float4*)(Hn + e * 260);
                const float4* B4 = (const float4*)(Q + c * Ddim);
                float s = 0.f;
#pragma unroll
                for (int k = 0; k < 64; ++k) {
                    float4 a = A[k], bb = B4[k];
                    s += a.x * bb.x + a.y * bb.y + a.z * bb.z + a.w * bb.w;
                }
                M[e * 32 + c] = s;
            }
            __syncthreads();

            // scan: one thread per class, no barriers
            if (tid < 32) {
                int c = tid;
                float n2c = s_n2[c];
                unsigned long long mask = 0ull;
                for (int e = 0; e < cl; ++e) {
                    float num = M[e * 32 + c];
                    unsigned long long mm = mask;
                    while (mm) {
                        int e2 = __ffsll((long long)mm) - 1;
                        mm &= mm - 1;
                        num += G[e * 64 + e2];
                    }
                    bool valid = ev_pc[c0 + e] > 0;
                    SB[e * 32 + c] = valid ? scale * num * rsqrtf(n2c) : 0.f;
                    if (ev_n[c0 + e] - clo == c) {
                        n2c += 2.f * num + G[e * 64 + e];
                        mask |= 1ull << e;
                    }
                }
                s_n2[c] = n2c;
            }
            __syncthreads();

            // write sims; update Q with chunk supports
            for (int idx = tid; idx < cl * 32; idx += 512) {
                int e = idx >> 5, c = idx & 31;
                g_scr[((long)b * Tdim + ev_t[c0 + e]) * 96 + cbase + c] = SB[e * 32 + c];
            }
            for (int e = 0; e < cl; ++e) {
                int cc = ev_n[c0 + e] - clo;
                if (cc >= 0 && cc < 32) {
                    if (tid < 256) Q[cc * Ddim + tid] += Hn[e * 260 + tid];
                }
            }
            __syncthreads();
        }

        __syncthreads();
        if (tid == 0) {
            __threadfence();
            atomicAdd(&g_done[b], 1);
        }
    }
}

extern "C" void kernel_launch(void* const* d_in, const int* in_sizes, int n_in,
                              void* d_out, int out_size)
{
    cudaFuncSetAttribute(fat_kernel, cudaFuncAttributeMaxDynamicSharedMemorySize, SMEM_BYTES);

    reset_kernel<<<1, 32>>>();

    fat_kernel<<<152, 512, SMEM_BYTES>>>(
        (const int*)d_in[0], (const float*)d_in[1], (const float*)d_in[2],
        (const float*)d_in[3], (const float*)d_in[4],
        (const float*)d_in[5], (const float*)d_in[6],
        (const float*)d_in[7], (const float*)d_in[8],
        (const float*)d_in[9], (const float*)d_in[10],
        (const float*)d_in[11], (const float*)d_in[12],
        (const float*)d_in[13], (const float*)d_in[14],
        (float*)d_out);
}

// round 11
// speedup vs baseline: 1.3637x; 1.3637x over previous
#include <cuda_runtime.h>
#include <math.h>
#include <stdint.h>

#define Tdim 2048
#define Ddim 256
#define CACT 64
#define CTIME 32
#define NROWS (8 * 2048)
#define LABEL_ID_ 3
#define OBSTR 98
#define CHUNK 64

// dynamic smem layout (gemm role), byte offsets
#define B_HI 0                  // 256 x 208B  ([k][96n bf16 + 8 pad])
#define B_LO 53248
#define A_HI 106496             // 128 x 256B  (one K-half, swizzled)
#define A_LO 139264
#define SMEM_BYTES 172032

// proto smem layout (float offsets), rows have stride 260
#define P_Q    0                // 32 x 260
#define P_HN   8320             // 64 x 260
#define P_G    24960            // 64 x 64
#define P_M    29056            // 64 x 32
#define P_SB   31104            // 64 x 32
#define P_INT  33152            // ints: toks, ev_t, ev_n, ev_pc (4 x 2048)

__device__ float g_scr[(long)NROWS * 96];
__device__ int   g_done[8];

__device__ __forceinline__ float softplusf(float x) { return log1pf(expf(x)); }

__device__ __forceinline__ uint32_t smem_u32(const void* p) {
    uint32_t a;
    asm("{ .reg .u64 t; cvta.to.shared.u64 t, %1; cvt.u32.u64 %0, t; }" : "=r"(a) : "l"(p));
    return a;
}
__device__ __forceinline__ void hilo2(float x0, float x1, uint32_t& hi, uint32_t& lo) {
    asm("cvt.rn.bf16x2.f32 %0, %1, %2;" : "=r"(hi) : "f"(x1), "f"(x0));
    float h0 = __uint_as_float(hi << 16);
    float h1 = __uint_as_float(hi & 0xffff0000u);
    asm("cvt.rn.bf16x2.f32 %0, %1, %2;" : "=r"(lo) : "f"(x1 - h1), "f"(x0 - h0));
}
__device__ __forceinline__ void ldsm4(uint32_t addr, uint32_t& r0, uint32_t& r1,
                                      uint32_t& r2, uint32_t& r3) {
    asm volatile("ldmatrix.sync.aligned.m8n8.x4.shared.b16 {%0,%1,%2,%3}, [%4];"
                 : "=r"(r0), "=r"(r1), "=r"(r2), "=r"(r3) : "r"(addr));
}
__device__ __forceinline__ void ldsm4t(uint32_t addr, uint32_t& r0, uint32_t& r1,
                                       uint32_t& r2, uint32_t& r3) {
    asm volatile("ldmatrix.sync.aligned.m8n8.x4.trans.shared.b16 {%0,%1,%2,%3}, [%4];"
                 : "=r"(r0), "=r"(r1), "=r"(r2), "=r"(r3) : "r"(addr));
}
__device__ __forceinline__ void mma16816(float* c, uint32_t a0, uint32_t a1,
                                         uint32_t a2, uint32_t a3,
                                         uint32_t b0, uint32_t b1) {
    asm volatile(
        "mma.sync.aligned.m16n8k16.row.col.f32.bf16.bf16.f32 "
        "{%0,%1,%2,%3},{%4,%5,%6,%7},{%8,%9},{%0,%1,%2,%3};"
        : "+f"(c[0]), "+f"(c[1]), "+f"(c[2]), "+f"(c[3])
        : "r"(a0), "r"(a1), "r"(a2), "r"(a3), "r"(b0), "r"(b1));
}

__global__ void reset_kernel() {
    if (threadIdx.x < 8) g_done[threadIdx.x] = 0;
}

__global__ void __launch_bounds__(512, 1) fat_kernel(
    const int* __restrict__ tokens, const float* __restrict__ h,
    const float* __restrict__ E,
    const float* __restrict__ Wn, const float* __restrict__ bn,
    const float* __restrict__ Wt, const float* __restrict__ bt,
    const float* __restrict__ tsa, const float* __restrict__ tst,
    const float* __restrict__ psa, const float* __restrict__ pst,
    const float* __restrict__ ppa, const float* __restrict__ ppt,
    const float* __restrict__ pta, const float* __restrict__ ptt,
    float* __restrict__ out)
{
    extern __shared__ char smc[];
    float* sm = (float*)smc;
    int tid = threadIdx.x, lane = tid & 31, wid = tid >> 5;
    int bx = blockIdx.x;

    if (bx >= 24) {
        // =============== GEMM role: HMMA bf16 hi/lo split (verbatim R9) ===============
        __shared__ float s_bias[96];
        __shared__ int s_lab[128];
        __shared__ int s_nlab;

        long rowbase = (long)(bx - 24) * 128;
        int b = (int)(rowbase >> 11);
        float s_ta = softplusf(*tsa), s_tt = softplusf(*tst);

        if (tid == 0) s_nlab = 0;
        if (tid < 96) s_bias[tid] = (tid < CACT) ? bn[tid] : bt[tid - CACT];

        uint32_t smem_base = smem_u32(smc);
        int rt = wid >> 1;
        int ch = wid & 1;

        float acc[6][4];
#pragma unroll
        for (int j = 0; j < 6; ++j)
#pragma unroll
            for (int i = 0; i < 4; ++i) acc[j][i] = 0.f;

        {
            const float2* E2 = (const float2*)E;
#pragma unroll
            for (int it = 0; it < 24; ++it) {
                int i = tid + 512 * it;
                int c = i >> 7, kp = i & 127;
                const float2* wrow = (const float2*)((c < CACT) ? (Wn + c * Ddim)
                                                                : (Wt + (c - CACT) * Ddim));
                int erow = (c < CACT) ? (4 + c) : (68 + (c - CACT));
                float sc = (c < CACT) ? s_ta : s_tt;
                float2 wv = wrow[kp];
                float2 ev = E2[erow * 128 + kp];
                float x0 = fmaf(sc, ev.x, wv.x), x1 = fmaf(sc, ev.y, wv.y);
                uint32_t hi, lo;
                hilo2(x0, x1, hi, lo);
                int k = 2 * kp;
                *(unsigned short*)(smc + B_HI + k * 208 + c * 2)       = (unsigned short)(hi & 0xffff);
                *(unsigned short*)(smc + B_HI + (k + 1) * 208 + c * 2) = (unsigned short)(hi >> 16);
                *(unsigned short*)(smc + B_LO + k * 208 + c * 2)       = (unsigned short)(lo & 0xffff);
                *(unsigned short*)(smc + B_LO + (k + 1) * 208 + c * 2) = (unsigned short)(lo >> 16);
            }
        }

        const float4* gh4 = (const float4*)h;
        int a_row = rt * 16 + (lane & 15);
        int a_half = lane >> 4;
        int b_kl = ((lane & 8) ? 8 : 0) + (lane & 7);
        int b_ntsel = (lane < 16) ? 0 : 1;

        for (int s = 0; s < 2; ++s) {
            __syncthreads();
#pragma unroll
            for (int it = 0; it < 4; ++it) {
                int i = tid + 512 * it;
                int r = i >> 4, c = i & 15;
                float4 v0 = gh4[(rowbase + r) * 64 + s * 32 + 2 * c];
                float4 v1 = gh4[(rowbase + r) * 64 + s * 32 + 2 * c + 1];
                uint4 hi4, lo4;
                hilo2(v0.x, v0.y, hi4.x, lo4.x);
                hilo2(v0.z, v0.w, hi4.y, lo4.y);
                hilo2(v1.x, v1.y, hi4.z, lo4.z);
                hilo2(v1.z, v1.w, hi4.w, lo4.w);
                int sw = (c ^ (r & 7)) * 16;
                *(uint4*)(smc + A_HI + r * 256 + sw) = hi4;
                *(uint4*)(smc + A_LO + r * 256 + sw) = lo4;
            }
            __syncthreads();

#pragma unroll
            for (int kc = 0; kc < 8; ++kc) {
                int chunk = kc * 2 + a_half;
                uint32_t a_off = a_row * 256 + ((chunk ^ (a_row & 7)) * 16);
                uint32_t aH0, aH1, aH2, aH3, aL0, aL1, aL2, aL3;
                ldsm4(smem_base + A_HI + a_off, aH0, aH1, aH2, aH3);
                ldsm4(smem_base + A_LO + a_off, aL0, aL1, aL2, aL3);

                int k0 = s * 128 + kc * 16;
                uint32_t bH[12], bL[12];
#pragma unroll
                for (int j2 = 0; j2 < 3; ++j2) {
                    int nof = ch * 48 + j2 * 16 + b_ntsel * 8;
                    uint32_t b_off = (k0 + b_kl) * 208 + nof * 2;
                    ldsm4t(smem_base + B_HI + b_off,
                           bH[4 * j2 + 0], bH[4 * j2 + 1], bH[4 * j2 + 2], bH[4 * j2 + 3]);
                    ldsm4t(smem_base + B_LO + b_off,
                           bL[4 * j2 + 0], bL[4 * j2 + 1], bL[4 * j2 + 2], bL[4 * j2 + 3]);
                }
#pragma unroll
                for (int j = 0; j < 6; ++j) {
                    mma16816(acc[j], aH0, aH1, aH2, aH3, bH[2 * j], bH[2 * j + 1]);
                    mma16816(acc[j], aH0, aH1, aH2, aH3, bL[2 * j], bL[2 * j + 1]);
                    mma16816(acc[j], aL0, aL1, aL2, aL3, bH[2 * j], bH[2 * j + 1]);
                }
            }
        }

        if (tid < 128) {
            int tok = tokens[rowbase + tid];
            if (tok == LABEL_ID_) {
                int idx = atomicAdd(&s_nlab, 1);
                s_lab[idx] = tid;
            }
        }

        __syncthreads();
        float* ob = sm;
        {
            int r0 = rt * 16 + (lane >> 2);
            int cb = ch * 48 + 2 * (lane & 3);
#pragma unroll
            for (int j = 0; j < 6; ++j) {
                int col = cb + 8 * j;
                float2 v0 = make_float2(acc[j][0] + s_bias[col], acc[j][1] + s_bias[col + 1]);
                float2 v1 = make_float2(acc[j][2] + s_bias[col], acc[j][3] + s_bias[col + 1]);
                *(float2*)(ob + r0 * OBSTR + col) = v0;
                *(float2*)(ob + (r0 + 8) * OBSTR + col) = v1;
            }
        }
        if (tid == 0) {
            while (*(volatile int*)&g_done[b] < 3) __nanosleep(64);
        }
        __syncthreads();
        int nlab = s_nlab;
        for (int i = 0; i < nlab; ++i) {
            int r = s_lab[i];
            if (tid < 96)
                ob[r * OBSTR + tid] += __ldcg(&g_scr[(rowbase + r) * 96 + tid]);
        }
        __syncthreads();

        float* outT = out + (long)NROWS * CACT;
#pragma unroll
        for (int k = 0; k < 8; ++k) {
            int i = tid + 512 * k;
            int r = i >> 5, c2 = i & 31;
            float2 v = *(float2*)(ob + r * OBSTR + 2 * c2);
            *(float2*)(out + (rowbase + r) * CACT + 2 * c2) = v;
        }
#pragma unroll
        for (int k = 0; k < 4; ++k) {
            int i = tid + 512 * k;
            int r = i >> 4, c2 = i & 15;
            float2 v = *(float2*)(ob + r * OBSTR + CACT + 2 * c2);
            *(float2*)(outT + (rowbase + r) * CTIME + 2 * c2) = v;
        }
    } else {
        // =============== proto role: G/M with register-blocked dots ===============
        int b = bx / 3, part = bx % 3;
        int clo = (part == 0) ? 4 : (part == 1) ? 36 : 68;
        int klo = (part == 2) ? 68 : 4;
        int khi = (part == 2) ? 100 : 68;
        int cbase = part * 32;

        float* Q  = sm + P_Q;       // 32 x 260: q0 + carry of past-chunk supports
        float* Hn = sm + P_HN;      // 64 x 260
        float* G  = sm + P_G;       // 64 x 64
        float* M  = sm + P_M;       // 64 x 32
        float* SB = sm + P_SB;      // 64 x 32
        int* toks  = (int*)(sm + P_INT);
        int* ev_t  = toks + Tdim;
        int* ev_n  = ev_t + Tdim;
        int* ev_pc = ev_n + Tdim;
        __shared__ int s_nev;
        __shared__ float s_n2[32];

        for (int i = tid; i < Tdim; i += 512) toks[i] = tokens[(long)b * Tdim + i];
        __syncthreads();

        if (wid == 0) {
            int cnt = 0;
            for (int ch2 = 0; ch2 < Tdim / 32; ++ch2) {
                int t = ch2 * 32 + lane;
                bool isl = (toks[t] == LABEL_ID_);
                unsigned m = __ballot_sync(0xffffffffu, isl);
                if (isl) {
                    int idx = cnt + __popc(m & ((1u << lane) - 1u));
                    ev_t[idx] = t;
                    ev_n[idx] = toks[(t + 1) & (Tdim - 1)];
                }
                cnt += __popc(m);
            }
            if (lane == 0) {
                s_nev = cnt;
                int run = 0;
                for (int e = 0; e < cnt; ++e) {
                    ev_pc[e] = run;
                    int nt = ev_n[e];
                    if (nt >= klo && nt < khi) run++;
                }
            }
        }

        float alpha = softplusf(part == 2 ? *ppt : *ppa);
        float scale = softplusf(part == 2 ? *pst : *psa) * softplusf(part == 2 ? *ptt : *pta);

        // Q init = alpha * l2norm(E[clo+c]), stride 260
        for (int c = wid; c < 32; c += 16) {
            const float* e = E + (long)(clo + c) * Ddim;
            float v[8]; float ss = 0.f;
#pragma unroll
            for (int k = 0; k < 8; ++k) { v[k] = e[lane + 32 * k]; ss += v[k] * v[k]; }
#pragma unroll
            for (int o = 16; o > 0; o >>= 1) ss += __shfl_xor_sync(0xffffffffu, ss, o);
            float inv = alpha / fmaxf(sqrtf(ss), 1e-12f);
#pragma unroll
            for (int k = 0; k < 8; ++k) Q[c * 260 + lane + 32 * k] = v[k] * inv;
        }
        if (tid < 32) s_n2[tid] = alpha * alpha;
        __syncthreads();

        int nev = s_nev;
        const float* hb = h + (long)b * Tdim * Ddim;

        for (int c0 = 0; c0 < nev; c0 += CHUNK) {
            int cl = min(CHUNK, nev - c0);

            // load + normalize chunk h rows (warp per row)
            for (int r = wid; r < cl; r += 16) {
                const float* hr = hb + (long)ev_t[c0 + r] * Ddim;
                float v[8]; float ss = 0.f;
#pragma unroll
                for (int k = 0; k < 8; ++k) { v[k] = hr[lane + 32 * k]; ss += v[k] * v[k]; }
#pragma unroll
                for (int o = 16; o > 0; o >>= 1) ss += __shfl_xor_sync(0xffffffffu, ss, o);
                float inv = 1.0f / fmaxf(sqrtf(ss), 1e-12f);
#pragma unroll
                for (int k = 0; k < 8; ++k) Hn[r * 260 + lane + 32 * k] = v[k] * inv;
            }
            __syncthreads();

            // M[e][c] = q_c . hn_e : thread = (c, seg16), q cached in 16 regs
            {
                int c = tid >> 4, seg = tid & 15;
                float qv[16];
#pragma unroll
                for (int k = 0; k < 16; ++k)
                    qv[k] = Q[c * 260 + seg * 16 + ((k + 2 * seg) & 15)];
                for (int e = 0; e < cl; ++e) {
                    const float* he = Hn + e * 260 + seg * 16;
                    float s = 0.f;
#pragma unroll
                    for (int k = 0; k < 16; ++k)
                        s += qv[k] * he[(k + 2 * seg) & 15];
                    s += __shfl_xor_sync(0xffffffffu, s, 8);
                    s += __shfl_xor_sync(0xffffffffu, s, 4);
                    s += __shfl_xor_sync(0xffffffffu, s, 2);
                    s += __shfl_xor_sync(0xffffffffu, s, 1);
                    if (seg == 0) M[e * 32 + c] = s;
                }
            }
            // G[e][j] = hn_j . hn_e : thread = (j, seg8), hn_j cached in 32 regs
            {
                int j = tid >> 3, seg = tid & 7;
                float hv[32];
#pragma unroll
                for (int k = 0; k < 32; ++k)
                    hv[k] = (j < cl) ? Hn[j * 260 + seg * 32 + ((k + 4 * seg) & 31)] : 0.f;
                for (int e = 0; e < cl; ++e) {
                    const float* he = Hn + e * 260 + seg * 32;
                    float s = 0.f;
#pragma unroll
                    for (int k = 0; k < 32; ++k)
                        s += hv[k] * he[(k + 4 * seg) & 31];
                    s += __shfl_xor_sync(0xffffffffu, s, 4);
                    s += __shfl_xor_sync(0xffffffffu, s, 2);
                    s += __shfl_xor_sync(0xffffffffu, s, 1);
                    if (seg == 0 && j < cl) G[e * 64 + j] = s;
                }
            }
            __syncthreads();

            // scan: one thread per class, no barriers
            if (tid < 32) {
                int c = tid;
                float n2c = s_n2[c];
                unsigned long long mask = 0ull;
                for (int e = 0; e < cl; ++e) {
                    float num = M[e * 32 + c];
                    unsigned long long mm = mask;
                    while (mm) {
                        int e2 = __ffsll((long long)mm) - 1;
                        mm &= mm - 1;
                        num += G[e * 64 + e2];
                    }
                    bool valid = ev_pc[c0 + e] > 0;
                    SB[e * 32 + c] = valid ? scale * num * rsqrtf(n2c) : 0.f;
                    if (ev_n[c0 + e] - clo == c) {
                        n2c += 2.f * num + G[e * 64 + e];
                        mask |= 1ull << e;
                    }
                }
                s_n2[c] = n2c;
            }
            __syncthreads();

            // write sims
            for (int idx = tid; idx < cl * 32; idx += 512) {
                int e = idx >> 5, c = idx & 31;
                g_scr[((long)b * Tdim + ev_t[c0 + e]) * 96 + cbase + c] = SB[e * 32 + c];
            }
            // carry Q forward only if another chunk follows
            if (c0 + CHUNK < nev) {
                __syncthreads();
                for (int e = 0; e < cl; ++e) {
                    int cc = ev_n[c0 + e] - clo;
                    if (cc >= 0 && cc < 32 && tid < 256)
                        Q[cc * 260 + tid] += Hn[e * 260 + tid];
                }
                __syncthreads();
            }
        }

        __syncthreads();
        if (tid == 0) {
            __threadfence();
            atomicAdd(&g_done[b], 1);
        }
    }
}

extern "C" void kernel_launch(void* const* d_in, const int* in_sizes, int n_in,
                              void* d_out, int out_size)
{
    cudaFuncSetAttribute(fat_kernel, cudaFuncAttributeMaxDynamicSharedMemorySize, SMEM_BYTES);

    reset_kernel<<<1, 32>>>();

    fat_kernel<<<152, 512, SMEM_BYTES>>>(
        (const int*)d_in[0], (const float*)d_in[1], (const float*)d_in[2],
        (const float*)d_in[3], (const float*)d_in[4],
        (const float*)d_in[5], (const float*)d_in[6],
        (const float*)d_in[7], (const float*)d_in[8],
        (const float*)d_in[9], (const float*)d_in[10],
        (const float*)d_in[11], (const float*)d_in[12],
        (const float*)d_in[13], (const float*)d_in[14],
        (float*)d_out);
}

// round 13
// speedup vs baseline: 1.4213x; 1.0422x over previous
#include <cuda_runtime.h>
#include <math.h>
#include <stdint.h>

#define Tdim 2048
#define Ddim 256
#define CACT 64
#define CTIME 32
#define NROWS (8 * 2048)
#define LABEL_ID_ 3
#define CHUNK 32

// ---- gemm smem (byte offsets), block = 128 rows x 48 cols ----
#define B_HI 0                    // 48 x 132 u32 (packed bf16 k-pairs)
#define B_LO 25344
#define A_HI 50688                // 128 rows x 128B (one K-quarter)
#define A_LO 67072                // -> 83456
// ---- proto smem (float offsets) ----
#define P_Q   0                   // 32 x 260
#define P_HN  8320                // 32 x 260
#define P_G   16640               // 32 x 32
#define P_M   17664
#define P_SB  18688
#define P_TOK 19712               // 2048 ints
#define SMEM_BYTES 88064

__device__ float g_scr[(long)NROWS * 96];
__device__ int   g_done[8];
__device__ int   g_evt[24 * Tdim];
__device__ int   g_evn[24 * Tdim];

__device__ __forceinline__ float softplusf(float x) { return log1pf(expf(x)); }

__device__ __forceinline__ uint32_t smem_u32(const void* p) {
    uint32_t a;
    asm("{ .reg .u64 t; cvta.to.shared.u64 t, %1; cvt.u32.u64 %0, t; }" : "=r"(a) : "l"(p));
    return a;
}
__device__ __forceinline__ void hilo2(float x0, float x1, uint32_t& hi, uint32_t& lo) {
    asm("cvt.rn.bf16x2.f32 %0, %1, %2;" : "=r"(hi) : "f"(x1), "f"(x0));
    float h0 = __uint_as_float(hi << 16);
    float h1 = __uint_as_float(hi & 0xffff0000u);
    asm("cvt.rn.bf16x2.f32 %0, %1, %2;" : "=r"(lo) : "f"(x1 - h1), "f"(x0 - h0));
}
__device__ __forceinline__ void ldsm4(uint32_t addr, uint32_t& r0, uint32_t& r1,
                                      uint32_t& r2, uint32_t& r3) {
    asm volatile("ldmatrix.sync.aligned.m8n8.x4.shared.b16 {%0,%1,%2,%3}, [%4];"
                 : "=r"(r0), "=r"(r1), "=r"(r2), "=r"(r3) : "r"(addr));
}
__device__ __forceinline__ void mma16816(float* c, uint32_t a0, uint32_t a1,
                                         uint32_t a2, uint32_t a3,
                                         uint32_t b0, uint32_t b1) {
    asm volatile(
        "mma.sync.aligned.m16n8k16.row.col.f32.bf16.bf16.f32 "
        "{%0,%1,%2,%3},{%4,%5,%6,%7},{%8,%9},{%0,%1,%2,%3};"
        : "+f"(c[0]), "+f"(c[1]), "+f"(c[2]), "+f"(c[3])
        : "r"(a0), "r"(a1), "r"(a2), "r"(a3), "r"(b0), "r"(b1));
}

__global__ void reset_kernel() {
    if (threadIdx.x < 8) g_done[threadIdx.x] = 0;
}

__global__ void __launch_bounds__(256, 2) fat_kernel(
    const int* __restrict__ tokens, const float* __restrict__ h,
    const float* __restrict__ E,
    const float* __restrict__ Wn, const float* __restrict__ bn,
    const float* __restrict__ Wt, const float* __restrict__ bt,
    const float* __restrict__ tsa, const float* __restrict__ tst,
    const float* __restrict__ psa, const float* __restrict__ pst,
    const float* __restrict__ ppa, const float* __restrict__ ppt,
    const float* __restrict__ pta, const float* __restrict__ ptt,
    float* __restrict__ out)
{
    extern __shared__ char smc[];
    float* sm = (float*)smc;
    int tid = threadIdx.x, lane = tid & 31, wid = tid >> 5;
    int bx = blockIdx.x;

    if (bx >= 24) {
        // ============ GEMM role: 128 rows x 48 cols, HMMA hi/lo, 4 K-quarters ============
        __shared__ float s_bias[48];
        __shared__ int s_lab[128];
        __shared__ int s_nlab;

        int g = bx - 24;
        int half = g & 1;
        long rowbase = (long)(g >> 1) * 128;
        int b = (int)(rowbase >> 11);
        float s_ta = softplusf(*tsa), s_tt = softplusf(*tst);

        if (tid == 0) s_nlab = 0;
        if (tid < 48) {
            int c = half * 48 + tid;
            s_bias[tid] = (c < CACT) ? bn[c] : bt[c - CACT];
        }

        uint32_t* BH32 = (uint32_t*)(smc + B_HI);
        uint32_t* BL32 = (uint32_t*)(smc + B_LO);

        // ---- fold B half: 48 cols x 128 k-pairs, [n][kp] packed u32 ----
        {
            const float2* E2 = (const float2*)E;
#pragma unroll
            for (int it = 0; it < 24; ++it) {
                int i = tid + 256 * it;
                int c = i >> 7, kp = i & 127;
                int cg = half * 48 + c;
                const float2* wrow = (cg < CACT) ? (const float2*)(Wn + cg * Ddim)
                                                 : (const float2*)(Wt + (cg - CACT) * Ddim);
                int erow = (cg < CACT) ? (4 + cg) : (68 + (cg - CACT));
                float sc = (cg < CACT) ? s_ta : s_tt;
                float2 wv = wrow[kp];
                float2 ev = E2[erow * 128 + kp];
                float x0 = fmaf(sc, ev.x, wv.x), x1 = fmaf(sc, ev.y, wv.y);
                uint32_t hi, lo;
                hilo2(x0, x1, hi, lo);
                BH32[c * 132 + kp] = hi;
                BL32[c * 132 + kp] = lo;
            }
        }

        float acc[6][4];
#pragma unroll
        for (int j = 0; j < 6; ++j)
#pragma unroll
            for (int i = 0; i < 4; ++i) acc[j][i] = 0.f;

        uint32_t smem_base = smem_u32(smc);
        const float4* gh4 = (const float4*)h;
        int rt = wid;                      // row tile 0..7 (16 rows each)
        int a_row = rt * 16 + (lane & 15);
        int a_half = lane >> 4;

        for (int q = 0; q < 4; ++q) {
            __syncthreads();
            // stage A K-quarter: 128 rows x 64 k -> swizzled hi/lo (128B rows)
#pragma unroll
            for (int it = 0; it < 4; ++it) {
                int i = tid + 256 * it;
                int r = i >> 3, c = i & 7;
                float4 v0 = gh4[(rowbase + r) * 64 + q * 16 + 2 * c];
                float4 v1 = gh4[(rowbase + r) * 64 + q * 16 + 2 * c + 1];
                uint4 hi4, lo4;
                hilo2(v0.x, v0.y, hi4.x, lo4.x);
                hilo2(v0.z, v0.w, hi4.y, lo4.y);
                hilo2(v1.x, v1.y, hi4.z, lo4.z);
                hilo2(v1.z, v1.w, hi4.w, lo4.w);
                int sw = (c ^ (r & 7)) * 16;
                *(uint4*)(smc + A_HI + r * 128 + sw) = hi4;
                *(uint4*)(smc + A_LO + r * 128 + sw) = lo4;
            }
            __syncthreads();

#pragma unroll
            for (int kc = 0; kc < 4; ++kc) {
                int chunk = kc * 2 + a_half;
                uint32_t a_off = a_row * 128 + ((chunk ^ (a_row & 7)) * 16);
                uint32_t aH0, aH1, aH2, aH3, aL0, aL1, aL2, aL3;
                ldsm4(smem_base + A_HI + a_off, aH0, aH1, aH2, aH3);
                ldsm4(smem_base + A_LO + a_off, aL0, aL1, aL2, aL3);

                int kpb = q * 32 + kc * 8;
#pragma unroll
                for (int j = 0; j < 6; ++j) {
                    int idx0 = (j * 8 + (lane >> 2)) * 132 + kpb + (lane & 3);
                    uint32_t bh0 = BH32[idx0], bh1 = BH32[idx0 + 4];
                    uint32_t bl0 = BL32[idx0], bl1 = BL32[idx0 + 4];
                    mma16816(acc[j], aH0, aH1, aH2, aH3, bh0, bh1);
                    mma16816(acc[j], aH0, aH1, aH2, aH3, bl0, bl1);
                    mma16816(acc[j], aL0, aL1, aL2, aL3, bh0, bh1);
                }
            }
        }

        // label rows of this 128-row tile
        if (tid < 128) {
            if (tokens[rowbase + tid] == LABEL_ID_) {
                int idx = atomicAdd(&s_nlab, 1);
                s_lab[idx] = tid;
            }
        }

        // ---- epilogue: stage 128 x 48 to ob (reuse B region) ----
        __syncthreads();
        float* ob = sm;                    // 128 x 52 floats = 26624B < B region
        {
            int r0 = rt * 16 + (lane >> 2);
            int cb = 2 * (lane & 3);
#pragma unroll
            for (int j = 0; j < 6; ++j) {
                int col = cb + 8 * j;
                ob[r0 * 52 + col]           = acc[j][0] + s_bias[col];
                ob[r0 * 52 + col + 1]       = acc[j][1] + s_bias[col + 1];
                ob[(r0 + 8) * 52 + col]     = acc[j][2] + s_bias[col];
                ob[(r0 + 8) * 52 + col + 1] = acc[j][3] + s_bias[col + 1];
            }
        }
        if (tid == 0) {
            while (*(volatile int*)&g_done[b] < 3) __nanosleep(64);
        }
        __syncthreads();
        int nlab = s_nlab;
        for (int i = 0; i < nlab; ++i) {
            int r = s_lab[i];
            if (tid < 48)
                ob[r * 52 + tid] += __ldcg(&g_scr[(rowbase + r) * 96 + half * 48 + tid]);
        }
        __syncthreads();

        // ---- coalesced stores ----
        if (half == 0) {
            // 128 rows x 48 act cols = 1536 float4
#pragma unroll
            for (int it = 0; it < 6; ++it) {
                int i = tid + 256 * it;
                int r = i / 12, q2 = i % 12;
                float4 v = *(float4*)(ob + r * 52 + 4 * q2);
                *(float4*)(out + (rowbase + r) * CACT + 4 * q2) = v;
            }
        } else {
            // act cols 48..63: 512 float4
#pragma unroll
            for (int it = 0; it < 2; ++it) {
                int i = tid + 256 * it;
                int r = i >> 2, q2 = i & 3;
                float4 v = *(float4*)(ob + r * 52 + 4 * q2);
                *(float4*)(out + (rowbase + r) * CACT + 48 + 4 * q2) = v;
            }
            // time cols 0..31: 1024 float4
            float* outT = out + (long)NROWS * CACT;
#pragma unroll
            for (int it = 0; it < 4; ++it) {
                int i = tid + 256 * it;
                int r = i >> 3, q2 = i & 7;
                float4 v = *(float4*)(ob + r * 52 + 16 + 4 * q2);
                *(float4*)(outT + (rowbase + r) * CTIME + 4 * q2) = v;
            }
        }
    } else {
        // ============ proto role: G/M, CHUNK=32, 256 threads (verbatim R12) ============
        int pb = bx;
        int b = pb / 3, part = pb % 3;
        int clo = (part == 0) ? 4 : (part == 1) ? 36 : 68;
        int klo = (part == 2) ? 68 : 4;
        int khi = (part == 2) ? 100 : 68;
        int cbase = part * 32;

        float* Q  = sm + P_Q;
        float* Hn = sm + P_HN;
        float* G  = sm + P_G;
        float* M  = sm + P_M;
        float* SB = sm + P_SB;
        int* toks = (int*)(sm + P_TOK);
        __shared__ int s_nev, s_first;
        __shared__ float s_n2[32];

        for (int i = tid; i < Tdim; i += 256) toks[i] = tokens[(long)b * Tdim + i];
        __syncthreads();

        if (wid == 0) {
            int cnt = 0, first = 0x7fffffff;
            for (int ch = 0; ch < Tdim / 32; ++ch) {
                int t = ch * 32 + lane;
                bool isl = (toks[t] == LABEL_ID_);
                unsigned m = __ballot_sync(0xffffffffu, isl);
                int ntok = isl ? toks[(t + 1) & (Tdim - 1)] : 0;
                if (isl) {
                    int idx = cnt + __popc(m & ((1u << lane) - 1u));
                    g_evt[pb * Tdim + idx] = t;
                    g_evn[pb * Tdim + idx] = ntok;
                }
                unsigned m2 = __ballot_sync(0xffffffffu, isl && ntok >= klo && ntok < khi);
                if (lane == 0 && m2 && first == 0x7fffffff) {
                    int l2 = __ffs(m2) - 1;
                    first = cnt + __popc(m & ((1u << l2) - 1u));
                }
                cnt += __popc(m);
            }
            if (lane == 0) { s_nev = cnt; s_first = first; }
        }

        float alpha = softplusf(part == 2 ? *ppt : *ppa);
        float scale = softplusf(part == 2 ? *pst : *psa) * softplusf(part == 2 ? *ptt : *pta);

        for (int c = wid; c < 32; c += 8) {
            const float* e = E + (long)(clo + c) * Ddim;
            float v[8]; float ss = 0.f;
#pragma unroll
            for (int k = 0; k < 8; ++k) { v[k] = e[lane + 32 * k]; ss += v[k] * v[k]; }
#pragma unroll
            for (int o = 16; o > 0; o >>= 1) ss += __shfl_xor_sync(0xffffffffu, ss, o);
            float inv = alpha / fmaxf(sqrtf(ss), 1e-12f);
#pragma unroll
            for (int k = 0; k < 8; ++k) Q[c * 260 + lane + 32 * k] = v[k] * inv;
        }
        if (tid < 32) s_n2[tid] = alpha * alpha;
        __syncthreads();

        int nev = s_nev, first_sup = s_first;
        const float* hb = h + (long)b * Tdim * Ddim;

        for (int c0 = 0; c0 < nev; c0 += CHUNK) {
            int cl = min(CHUNK, nev - c0);

            for (int r = wid; r < cl; r += 8) {
                const float* hr = hb + (long)g_evt[pb * Tdim + c0 + r] * Ddim;
                float v[8]; float ss = 0.f;
#pragma unroll
                for (int k = 0; k < 8; ++k) { v[k] = hr[lane + 32 * k]; ss += v[k] * v[k]; }
#pragma unroll
                for (int o = 16; o > 0; o >>= 1) ss += __shfl_xor_sync(0xffffffffu, ss, o);
                float inv = 1.0f / fmaxf(sqrtf(ss), 1e-12f);
#pragma unroll
                for (int k = 0; k < 8; ++k) Hn[r * 260 + lane + 32 * k] = v[k] * inv;
            }
            __syncthreads();

            int cc = tid >> 3, seg = tid & 7;
            {
                float qv[32];
#pragma unroll
                for (int k = 0; k < 32; ++k)
                    qv[k] = Q[cc * 260 + seg * 32 + ((k + 4 * seg) & 31)];
                for (int e = 0; e < cl; ++e) {
                    const float* he = Hn + e * 260 + seg * 32;
                    float s1 = 0.f;
#pragma unroll
                    for (int k = 0; k < 32; ++k)
                        s1 += qv[k] * he[(k + 4 * seg) & 31];
                    s1 += __shfl_xor_sync(0xffffffffu, s1, 4);
                    s1 += __shfl_xor_sync(0xffffffffu, s1, 2);
                    s1 += __shfl_xor_sync(0xffffffffu, s1, 1);
                    if (seg == 0) M[e * 32 + cc] = s1;
                }
            }
            {
                float hv[32];
#pragma unroll
                for (int k = 0; k < 32; ++k)
                    hv[k] = (cc < cl) ? Hn[cc * 260 + seg * 32 + ((k + 4 * seg) & 31)] : 0.f;
                for (int e = 0; e < cl; ++e) {
                    const float* he = Hn + e * 260 + seg * 32;
                    float s1 = 0.f;
#pragma unroll
                    for (int k = 0; k < 32; ++k)
                        s1 += hv[k] * he[(k + 4 * seg) & 31];
                    s1 += __shfl_xor_sync(0xffffffffu, s1, 4);
                    s1 += __shfl_xor_sync(0xffffffffu, s1, 2);
                    s1 += __shfl_xor_sync(0xffffffffu, s1, 1);
                    if (seg == 0 && cc < cl) G[e * 32 + cc] = s1;
                }
            }
            __syncthreads();

            if (tid < 32) {
                int c = tid;
                float n2c = s_n2[c];
                unsigned mask = 0u;
                for (int e = 0; e < cl; ++e) {
                    float num = M[e * 32 + c];
                    unsigned mm = mask;
                    while (mm) {
                        int e2 = __ffs(mm) - 1;
                        mm &= mm - 1;
                        num += G[e * 32 + e2];
                    }
                    SB[e * 32 + c] = (c0 + e > first_sup) ? scale * num * rsqrtf(n2c) : 0.f;
                    if (g_evn[pb * Tdim + c0 + e] - clo == c) {
                        n2c += 2.f * num + G[e * 32 + e];
                        mask |= 1u << e;
                    }
                }
                s_n2[c] = n2c;
            }
            __syncthreads();

            for (int idx = tid; idx < cl * 32; idx += 256) {
                int e = idx >> 5, c = idx & 31;
                g_scr[((long)b * Tdim + g_evt[pb * Tdim + c0 + e]) * 96 + cbase + c] = SB[e * 32 + c];
            }
            if (c0 + CHUNK < nev) {
                __syncthreads();
                for (int e = 0; e < cl; ++e) {
                    int c2 = g_evn[pb * Tdim + c0 + e] - clo;
                    if (c2 >= 0 && c2 < 32)
                        Q[c2 * 260 + tid] += Hn[e * 260 + tid];
                }
                __syncthreads();
            }
        }

        __syncthreads();
        if (tid == 0) {
            __threadfence();
            atomicAdd(&g_done[b], 1);
        }
    }
}

extern "C" void kernel_launch(void* const* d_in, const int* in_sizes, int n_in,
                              void* d_out, int out_size)
{
    cudaFuncSetAttribute(fat_kernel, cudaFuncAttributeMaxDynamicSharedMemorySize, SMEM_BYTES);

    reset_kernel<<<1, 32>>>();

    fat_kernel<<<24 + 256, 256, SMEM_BYTES>>>(
        (const int*)d_in[0], (const float*)d_in[1], (const float*)d_in[2],
        (const float*)d_in[3], (const float*)d_in[4],
        (const float*)d_in[5], (const float*)d_in[6],
        (const float*)d_in[7], (const float*)d_in[8],
        (const float*)d_in[9], (const float*)d_in[10],
        (const float*)d_in[11], (const float*)d_in[12],
        (const float*)d_in[13], (const float*)d_in[14],
        (float*)d_out);
}

// round 14
// speedup vs baseline: 1.5746x; 1.1079x over previous
#include <cuda_runtime.h>
#include <math.h>
#include <stdint.h>

#define Tdim 2048
#define Ddim 256
#define CACT 64
#define CTIME 32
#define NROWS (8 * 2048)
#define LABEL_ID_ 3
#define CHUNK 32

// ---- gemm smem (byte offsets), block = 128 rows x 48 cols ----
#define B_HI 0                    // 48 x 132 u32 (packed bf16 k-pairs)
#define B_LO 25344
#define A_HI 50688                // 128 rows x 128B (one K-quarter)
#define A_LO 67072                // -> 83456
// ---- proto smem (float offsets) ----
#define P_Q   0                   // 32 x 260
#define P_HN  8320                // 32 x 260
#define P_G   16640               // 32 x 32
#define P_M   17664               // 32 x 32
#define P_SB  18688               // 32 x 32 (num)
#define P_N2  19712               // 32 x 32 (sims out)
#define P_TOK 20736               // 2048 ints
#define SMEM_BYTES 91136

__device__ float g_scr[(long)NROWS * 96];
__device__ int   g_done[8];
__device__ int   g_evt[24 * Tdim];
__device__ int   g_evn[24 * Tdim];

__device__ __forceinline__ float softplusf(float x) { return log1pf(expf(x)); }

__device__ __forceinline__ uint32_t smem_u32(const void* p) {
    uint32_t a;
    asm("{ .reg .u64 t; cvta.to.shared.u64 t, %1; cvt.u32.u64 %0, t; }" : "=r"(a) : "l"(p));
    return a;
}
__device__ __forceinline__ void hilo2(float x0, float x1, uint32_t& hi, uint32_t& lo) {
    asm("cvt.rn.bf16x2.f32 %0, %1, %2;" : "=r"(hi) : "f"(x1), "f"(x0));
    float h0 = __uint_as_float(hi << 16);
    float h1 = __uint_as_float(hi & 0xffff0000u);
    asm("cvt.rn.bf16x2.f32 %0, %1, %2;" : "=r"(lo) : "f"(x1 - h1), "f"(x0 - h0));
}
__device__ __forceinline__ void ldsm4(uint32_t addr, uint32_t& r0, uint32_t& r1,
                                      uint32_t& r2, uint32_t& r3) {
    asm volatile("ldmatrix.sync.aligned.m8n8.x4.shared.b16 {%0,%1,%2,%3}, [%4];"
                 : "=r"(r0), "=r"(r1), "=r"(r2), "=r"(r3) : "r"(addr));
}
__device__ __forceinline__ void mma16816(float* c, uint32_t a0, uint32_t a1,
                                         uint32_t a2, uint32_t a3,
                                         uint32_t b0, uint32_t b1) {
    asm volatile(
        "mma.sync.aligned.m16n8k16.row.col.f32.bf16.bf16.f32 "
        "{%0,%1,%2,%3},{%4,%5,%6,%7},{%8,%9},{%0,%1,%2,%3};"
        : "+f"(c[0]), "+f"(c[1]), "+f"(c[2]), "+f"(c[3])
        : "r"(a0), "r"(a1), "r"(a2), "r"(a3), "r"(b0), "r"(b1));
}

__global__ void reset_kernel() {
    if (threadIdx.x < 8) g_done[threadIdx.x] = 0;
}

__global__ void __launch_bounds__(256, 2) fat_kernel(
    const int* __restrict__ tokens, const float* __restrict__ h,
    const float* __restrict__ E,
    const float* __restrict__ Wn, const float* __restrict__ bn,
    const float* __restrict__ Wt, const float* __restrict__ bt,
    const float* __restrict__ tsa, const float* __restrict__ tst,
    const float* __restrict__ psa, const float* __restrict__ pst,
    const float* __restrict__ ppa, const float* __restrict__ ppt,
    const float* __restrict__ pta, const float* __restrict__ ptt,
    float* __restrict__ out)
{
    extern __shared__ char smc[];
    float* sm = (float*)smc;
    int tid = threadIdx.x, lane = tid & 31, wid = tid >> 5;
    int bx = blockIdx.x;

    if (bx >= 24) {
        // ============ GEMM role: 128 rows x 48 cols, HMMA hi/lo, reg-prefetch pipeline ============
        __shared__ float s_bias[48];
        __shared__ int s_lab[128];
        __shared__ int s_nlab;

        int g = bx - 24;
        int half = g & 1;
        long rowbase = (long)(g >> 1) * 128;
        int b = (int)(rowbase >> 11);
        float s_ta = softplusf(*tsa), s_tt = softplusf(*tst);

        if (tid == 0) s_nlab = 0;
        if (tid < 48) {
            int c = half * 48 + tid;
            s_bias[tid] = (c < CACT) ? bn[c] : bt[c - CACT];
        }

        uint32_t* BH32 = (uint32_t*)(smc + B_HI);
        uint32_t* BL32 = (uint32_t*)(smc + B_LO);

        // ---- fold B half: 48 cols x 128 k-pairs, [n][kp] packed u32 ----
        {
            const float2* E2 = (const float2*)E;
#pragma unroll
            for (int it = 0; it < 24; ++it) {
                int i = tid + 256 * it;
                int c = i >> 7, kp = i & 127;
                int cg = half * 48 + c;
                const float2* wrow = (cg < CACT) ? (const float2*)(Wn + cg * Ddim)
                                                 : (const float2*)(Wt + (cg - CACT) * Ddim);
                int erow = (cg < CACT) ? (4 + cg) : (68 + (cg - CACT));
                float sc = (cg < CACT) ? s_ta : s_tt;
                float2 wv = wrow[kp];
                float2 ev = E2[erow * 128 + kp];
                float x0 = fmaf(sc, ev.x, wv.x), x1 = fmaf(sc, ev.y, wv.y);
                uint32_t hi, lo;
                hilo2(x0, x1, hi, lo);
                BH32[c * 132 + kp] = hi;
                BL32[c * 132 + kp] = lo;
            }
        }

        float acc[6][4];
#pragma unroll
        for (int j = 0; j < 6; ++j)
#pragma unroll
            for (int i = 0; i < 4; ++i) acc[j][i] = 0.f;

        uint32_t smem_base = smem_u32(smc);
        const float4* gh4 = (const float4*)h;
        int rt = wid;
        int a_row = rt * 16 + (lane & 15);
        int a_half = lane >> 4;
        int pr = tid >> 3, pc = tid & 7;            // prefetch coords: 4 rows x 2 f4 per thread per it... (r = i>>3)

        // prologue: prefetch quarter 0
        float4 pv0[4], pv1[4];
#pragma unroll
        for (int it = 0; it < 4; ++it) {
            int i = tid + 256 * it;
            int r = i >> 3, c = i & 7;
            pv0[it] = gh4[(rowbase + r) * 64 + 0 * 16 + 2 * c];
            pv1[it] = gh4[(rowbase + r) * 64 + 0 * 16 + 2 * c + 1];
        }

        for (int q = 0; q < 4; ++q) {
            __syncthreads();   // previous quarter's A reads complete
            // store prefetched quarter (convert hi/lo)
#pragma unroll
            for (int it = 0; it < 4; ++it) {
                int i = tid + 256 * it;
                int r = i >> 3, c = i & 7;
                uint4 hi4, lo4;
                hilo2(pv0[it].x, pv0[it].y, hi4.x, lo4.x);
                hilo2(pv0[it].z, pv0[it].w, hi4.y, lo4.y);
                hilo2(pv1[it].x, pv1[it].y, hi4.z, lo4.z);
                hilo2(pv1[it].z, pv1[it].w, hi4.w, lo4.w);
                int sw = (c ^ (r & 7)) * 16;
                *(uint4*)(smc + A_HI + r * 128 + sw) = hi4;
                *(uint4*)(smc + A_LO + r * 128 + sw) = lo4;
            }
            // prefetch next quarter BEFORE compute barrier (latency hidden by HMMA)
            if (q < 3) {
#pragma unroll
                for (int it = 0; it < 4; ++it) {
                    int i = tid + 256 * it;
                    int r = i >> 3, c = i & 7;
                    pv0[it] = gh4[(rowbase + r) * 64 + (q + 1) * 16 + 2 * c];
                    pv1[it] = gh4[(rowbase + r) * 64 + (q + 1) * 16 + 2 * c + 1];
                }
            }
            __syncthreads();   // staging visible

#pragma unroll
            for (int kc = 0; kc < 4; ++kc) {
                int chunk = kc * 2 + a_half;
                uint32_t a_off = a_row * 128 + ((chunk ^ (a_row & 7)) * 16);
                uint32_t aH0, aH1, aH2, aH3, aL0, aL1, aL2, aL3;
                ldsm4(smem_base + A_HI + a_off, aH0, aH1, aH2, aH3);
                ldsm4(smem_base + A_LO + a_off, aL0, aL1, aL2, aL3);

                int kpb = q * 32 + kc * 8;
#pragma unroll
                for (int j = 0; j < 6; ++j) {
                    int idx0 = (j * 8 + (lane >> 2)) * 132 + kpb + (lane & 3);
                    uint32_t bh0 = BH32[idx0], bh1 = BH32[idx0 + 4];
                    uint32_t bl0 = BL32[idx0], bl1 = BL32[idx0 + 4];
                    mma16816(acc[j], aH0, aH1, aH2, aH3, bh0, bh1);
                    mma16816(acc[j], aH0, aH1, aH2, aH3, bl0, bl1);
                    mma16816(acc[j], aL0, aL1, aL2, aL3, bh0, bh1);
                }
            }
        }

        // label rows of this 128-row tile
        if (tid < 128) {
            if (tokens[rowbase + tid] == LABEL_ID_) {
                int idx = atomicAdd(&s_nlab, 1);
                s_lab[idx] = tid;
            }
        }

        // ---- epilogue: stage 128 x 48 to ob (reuse B region) ----
        __syncthreads();
        float* ob = sm;
        {
            int r0 = rt * 16 + (lane >> 2);
            int cb = 2 * (lane & 3);
#pragma unroll
            for (int j = 0; j < 6; ++j) {
                int col = cb + 8 * j;
                ob[r0 * 52 + col]           = acc[j][0] + s_bias[col];
                ob[r0 * 52 + col + 1]       = acc[j][1] + s_bias[col + 1];
                ob[(r0 + 8) * 52 + col]     = acc[j][2] + s_bias[col];
                ob[(r0 + 8) * 52 + col + 1] = acc[j][3] + s_bias[col + 1];
            }
        }
        if (tid == 0) {
            while (*(volatile int*)&g_done[b] < 3) __nanosleep(64);
        }
        __syncthreads();
        int nlab = s_nlab;
        for (int i = 0; i < nlab; ++i) {
            int r = s_lab[i];
            if (tid < 48)
                ob[r * 52 + tid] += __ldcg(&g_scr[(rowbase + r) * 96 + half * 48 + tid]);
        }
        __syncthreads();

        // ---- coalesced stores ----
        if (half == 0) {
#pragma unroll
            for (int it = 0; it < 6; ++it) {
                int i = tid + 256 * it;
                int r = i / 12, q2 = i % 12;
                float4 v = *(float4*)(ob + r * 52 + 4 * q2);
                *(float4*)(out + (rowbase + r) * CACT + 4 * q2) = v;
            }
        } else {
#pragma unroll
            for (int it = 0; it < 2; ++it) {
                int i = tid + 256 * it;
                int r = i >> 2, q2 = i & 3;
                float4 v = *(float4*)(ob + r * 52 + 4 * q2);
                *(float4*)(out + (rowbase + r) * CACT + 48 + 4 * q2) = v;
            }
            float* outT = out + (long)NROWS * CACT;
#pragma unroll
            for (int it = 0; it < 4; ++it) {
                int i = tid + 256 * it;
                int r = i >> 3, q2 = i & 7;
                float4 v = *(float4*)(ob + r * 52 + 16 + 4 * q2);
                *(float4*)(outT + (rowbase + r) * CTIME + 4 * q2) = v;
            }
        }
    } else {
        // ============ proto role: fully parallel G/M closed form ============
        int pb = bx;
        int b = pb / 3, part = pb % 3;
        int clo = (part == 0) ? 4 : (part == 1) ? 36 : 68;
        int klo = (part == 2) ? 68 : 4;
        int khi = (part == 2) ? 100 : 68;
        int cbase = part * 32;

        float* Q   = sm + P_Q;
        float* Hn  = sm + P_HN;
        float* G   = sm + P_G;
        float* M   = sm + P_M;
        float* NUM = sm + P_SB;
        float* SIM = sm + P_N2;
        int* toks  = (int*)(sm + P_TOK);
        __shared__ int s_nev, s_first;
        __shared__ float s_n2[32];
        __shared__ int CL[CHUNK], TE[CHUNK];

        for (int i = tid; i < Tdim; i += 256) toks[i] = tokens[(long)b * Tdim + i];
        __syncthreads();

        float alpha = softplusf(part == 2 ? *ppt : *ppa);
        float scale = softplusf(part == 2 ? *pst : *psa) * softplusf(part == 2 ? *ptt : *pta);

        if (wid == 0) {
            // compact label events (warp 0) — overlapped with Q init below
            int cnt = 0, first = 0x7fffffff;
            for (int ch = 0; ch < Tdim / 32; ++ch) {
                int t = ch * 32 + lane;
                bool isl = (toks[t] == LABEL_ID_);
                unsigned m = __ballot_sync(0xffffffffu, isl);
                int ntok = isl ? toks[(t + 1) & (Tdim - 1)] : 0;
                if (isl) {
                    int idx = cnt + __popc(m & ((1u << lane) - 1u));
                    g_evt[pb * Tdim + idx] = t;
                    g_evn[pb * Tdim + idx] = ntok;
                }
                unsigned m2 = __ballot_sync(0xffffffffu, isl && ntok >= klo && ntok < khi);
                if (lane == 0 && m2 && first == 0x7fffffff) {
                    int l2 = __ffs(m2) - 1;
                    first = cnt + __popc(m & ((1u << l2) - 1u));
                }
                cnt += __popc(m);
            }
            if (lane == 0) { s_nev = cnt; s_first = first; }
        } else {
            // Q init = alpha * l2norm(E[clo+c])  (warps 1..7)
            for (int c = wid - 1; c < 32; c += 7) {
                const float* e = E + (long)(clo + c) * Ddim;
                float v[8]; float ss = 0.f;
#pragma unroll
                for (int k = 0; k < 8; ++k) { v[k] = e[lane + 32 * k]; ss += v[k] * v[k]; }
#pragma unroll
                for (int o = 16; o > 0; o >>= 1) ss += __shfl_xor_sync(0xffffffffu, ss, o);
                float inv = alpha / fmaxf(sqrtf(ss), 1e-12f);
#pragma unroll
                for (int k = 0; k < 8; ++k) Q[c * 260 + lane + 32 * k] = v[k] * inv;
            }
            if (wid == 1 && lane < 32) s_n2[lane] = alpha * alpha;
        }
        __syncthreads();

        int nev = s_nev, first_sup = s_first;
        const float* hb = h + (long)b * Tdim * Ddim;

        for (int c0 = 0; c0 < nev; c0 += CHUNK) {
            int cl = min(CHUNK, nev - c0);

            if (tid < cl) {
                TE[tid] = g_evt[pb * Tdim + c0 + tid];
                CL[tid] = g_evn[pb * Tdim + c0 + tid] - clo;   // may be out of [0,32)
            }
            __syncthreads();
            // load + normalize chunk rows
            for (int r = wid; r < cl; r += 8) {
                const float* hr = hb + (long)TE[r] * Ddim;
                float v[8]; float ss = 0.f;
#pragma unroll
                for (int k = 0; k < 8; ++k) { v[k] = hr[lane + 32 * k]; ss += v[k] * v[k]; }
#pragma unroll
                for (int o = 16; o > 0; o >>= 1) ss += __shfl_xor_sync(0xffffffffu, ss, o);
                float inv = 1.0f / fmaxf(sqrtf(ss), 1e-12f);
#pragma unroll
                for (int k = 0; k < 8; ++k) Hn[r * 260 + lane + 32 * k] = v[k] * inv;
            }
            __syncthreads();

            int cc = tid >> 3, seg = tid & 7;
            // M[e][c] = Q[c].Hn[e], 4 partial accumulators
            {
                float qv[32];
#pragma unroll
                for (int k = 0; k < 32; ++k)
                    qv[k] = Q[cc * 260 + seg * 32 + ((k + 4 * seg) & 31)];
                for (int e = 0; e < cl; ++e) {
                    const float* he = Hn + e * 260 + seg * 32;
                    float p0 = 0.f, p1 = 0.f, p2 = 0.f, p3 = 0.f;
#pragma unroll
                    for (int k = 0; k < 32; k += 4) {
                        p0 += qv[k]     * he[(k + 4 * seg) & 31];
                        p1 += qv[k + 1] * he[(k + 1 + 4 * seg) & 31];
                        p2 += qv[k + 2] * he[(k + 2 + 4 * seg) & 31];
                        p3 += qv[k + 3] * he[(k + 3 + 4 * seg) & 31];
                    }
                    float s1 = (p0 + p1) + (p2 + p3);
                    s1 += __shfl_xor_sync(0xffffffffu, s1, 4);
                    s1 += __shfl_xor_sync(0xffffffffu, s1, 2);
                    s1 += __shfl_xor_sync(0xffffffffu, s1, 1);
                    if (seg == 0) M[e * 32 + cc] = s1;
                }
            }
            // G[e][j] = Hn[j].Hn[e]
            {
                float hv[32];
#pragma unroll
                for (int k = 0; k < 32; ++k)
                    hv[k] = (cc < cl) ? Hn[cc * 260 + seg * 32 + ((k + 4 * seg) & 31)] : 0.f;
                for (int e = 0; e < cl; ++e) {
                    const float* he = Hn + e * 260 + seg * 32;
                    float p0 = 0.f, p1 = 0.f, p2 = 0.f, p3 = 0.f;
#pragma unroll
                    for (int k = 0; k < 32; k += 4) {
                        p0 += hv[k]     * he[(k + 4 * seg) & 31];
                        p1 += hv[k + 1] * he[(k + 1 + 4 * seg) & 31];
                        p2 += hv[k + 2] * he[(k + 2 + 4 * seg) & 31];
                        p3 += hv[k + 3] * he[(k + 3 + 4 * seg) & 31];
                    }
                    float s1 = (p0 + p1) + (p2 + p3);
                    s1 += __shfl_xor_sync(0xffffffffu, s1, 4);
                    s1 += __shfl_xor_sync(0xffffffffu, s1, 2);
                    s1 += __shfl_xor_sync(0xffffffffu, s1, 1);
                    if (seg == 0 && cc < cl) G[e * 32 + cc] = s1;
                }
            }
            __syncthreads();

            // NUM[e][c] = M[e][c] + sum_{e'<e, CL[e']==c} G[e][e']  (fully parallel)
            for (int idx = tid; idx < cl * 32; idx += 256) {
                int e = idx >> 5, c = idx & 31;
                float num = M[e * 32 + c];
                for (int e2 = 0; e2 < e; ++e2)
                    if (CL[e2] == c) num += G[e * 32 + e2];
                NUM[e * 32 + c] = num;
            }
            __syncthreads();
            // n2 prefix + sims  (fully parallel)
            for (int idx = tid; idx < cl * 32; idx += 256) {
                int e = idx >> 5, c = idx & 31;
                float n2 = s_n2[c];
                for (int e2 = 0; e2 < e; ++e2)
                    if (CL[e2] == c) n2 += 2.f * NUM[e2 * 32 + c] + G[e2 * 32 + e2];
                float num = NUM[e * 32 + c];
                SIM[e * 32 + c] = (c0 + e > first_sup) ? scale * num * rsqrtf(n2) : 0.f;
            }
            __syncthreads();

            // write sims
            for (int idx = tid; idx < cl * 32; idx += 256) {
                int e = idx >> 5, c = idx & 31;
                g_scr[((long)b * Tdim + TE[e]) * 96 + cbase + c] = SIM[e * 32 + c];
            }
            // carry to next chunk (rare)
            if (c0 + CHUNK < nev) {
                if (tid < 32) {
                    int c = tid;
                    float n2 = s_n2[c];
                    for (int e = 0; e < cl; ++e)
                        if (CL[e] == c) n2 += 2.f * NUM[e * 32 + c] + G[e * 32 + e];
                    s_n2[c] = n2;
                }
                __syncthreads();
                for (int e = 0; e < cl; ++e) {
                    int c2 = CL[e];
                    if (c2 >= 0 && c2 < 32)
                        Q[c2 * 260 + tid] += Hn[e * 260 + tid];
                }
                __syncthreads();
            }
        }

        __syncthreads();
        if (tid == 0) {
            __threadfence();
            atomicAdd(&g_done[b], 1);
        }
    }
}

extern "C" void kernel_launch(void* const* d_in, const int* in_sizes, int n_in,
                              void* d_out, int out_size)
{
    cudaFuncSetAttribute(fat_kernel, cudaFuncAttributeMaxDynamicSharedMemorySize, SMEM_BYTES);

    reset_kernel<<<1, 32>>>();

    fat_kernel<<<24 + 256, 256, SMEM_BYTES>>>(
        (const int*)d_in[0], (const float*)d_in[1], (const float*)d_in[2],
        (const float*)d_in[3], (const float*)d_in[4],
        (const float*)d_in[5], (const float*)d_in[6],
        (const float*)d_in[7], (const float*)d_in[8],
        (const float*)d_in[9], (const float*)d_in[10],
        (const float*)d_in[11], (const float*)d_in[12],
        (const float*)d_in[13], (const float*)d_in[14],
        (float*)d_out);
}

// round 15
// speedup vs baseline: 1.5846x; 1.0063x over previous
#include <cuda_runtime.h>
#include <math.h>
#include <stdint.h>

#define Tdim 2048
#define Ddim 256
#define CACT 64
#define CTIME 32
#define NROWS (8 * 2048)
#define LABEL_ID_ 3
#define CHUNK 32

// ---- gemm smem (byte offsets), block = 128 rows x 48 cols ----
#define B_HI 0                    // 48 x 132 u32 (packed bf16 k-pairs)
#define B_LO 25344
#define A_HI 50688                // 128 rows x 128B (one K-quarter)
#define A_LO 67072                // -> 83456
// ---- proto smem (float offsets) ----
#define P_Q   0                   // 32 x 260
#define P_HN  8320                // 32 x 260
#define P_G   16640               // 32 x 32
#define P_M   17664               // 32 x 32
#define P_SB  18688               // 32 x 32 (num)
#define P_N2  19712               // 32 x 32 (sims out)
#define P_TOK 20736               // 2048 ints
#define SMEM_BYTES 91136

__device__ float g_scr[(long)NROWS * 96];
__device__ int   g_evt[24 * Tdim];
__device__ int   g_evn[24 * Tdim];
__device__ int   g_nevd[24];

__device__ __forceinline__ float softplusf(float x) { return log1pf(expf(x)); }

__device__ __forceinline__ uint32_t smem_u32(const void* p) {
    uint32_t a;
    asm("{ .reg .u64 t; cvta.to.shared.u64 t, %1; cvt.u32.u64 %0, t; }" : "=r"(a) : "l"(p));
    return a;
}
__device__ __forceinline__ void hilo2(float x0, float x1, uint32_t& hi, uint32_t& lo) {
    asm("cvt.rn.bf16x2.f32 %0, %1, %2;" : "=r"(hi) : "f"(x1), "f"(x0));
    float h0 = __uint_as_float(hi << 16);
    float h1 = __uint_as_float(hi & 0xffff0000u);
    asm("cvt.rn.bf16x2.f32 %0, %1, %2;" : "=r"(lo) : "f"(x1 - h1), "f"(x0 - h0));
}
__device__ __forceinline__ void ldsm4(uint32_t addr, uint32_t& r0, uint32_t& r1,
                                      uint32_t& r2, uint32_t& r3) {
    asm volatile("ldmatrix.sync.aligned.m8n8.x4.shared.b16 {%0,%1,%2,%3}, [%4];"
                 : "=r"(r0), "=r"(r1), "=r"(r2), "=r"(r3) : "r"(addr));
}
__device__ __forceinline__ void mma16816(float* c, uint32_t a0, uint32_t a1,
                                         uint32_t a2, uint32_t a3,
                                         uint32_t b0, uint32_t b1) {
    asm volatile(
        "mma.sync.aligned.m16n8k16.row.col.f32.bf16.bf16.f32 "
        "{%0,%1,%2,%3},{%4,%5,%6,%7},{%8,%9},{%0,%1,%2,%3};"
        : "+f"(c[0]), "+f"(c[1]), "+f"(c[2]), "+f"(c[3])
        : "r"(a0), "r"(a1), "r"(a2), "r"(a3), "r"(b0), "r"(b1));
}

__global__ void __launch_bounds__(256, 2) fat_kernel(
    const int* __restrict__ tokens, const float* __restrict__ h,
    const float* __restrict__ E,
    const float* __restrict__ Wn, const float* __restrict__ bn,
    const float* __restrict__ Wt, const float* __restrict__ bt,
    const float* __restrict__ tsa, const float* __restrict__ tst,
    const float* __restrict__ psa, const float* __restrict__ pst,
    const float* __restrict__ ppa, const float* __restrict__ ppt,
    const float* __restrict__ pta, const float* __restrict__ ptt,
    float* __restrict__ out)
{
    extern __shared__ char smc[];
    float* sm = (float*)smc;
    int tid = threadIdx.x, lane = tid & 31, wid = tid >> 5;
    int bx = blockIdx.x;

    if (bx >= 24) {
        // ============ GEMM role: fully decoupled, direct stores ============
        __shared__ float s_bias[48];

        int g = bx - 24;
        int half = g & 1;
        long rowbase = (long)(g >> 1) * 128;
        float s_ta = softplusf(*tsa), s_tt = softplusf(*tst);

        if (tid < 48) {
            int c = half * 48 + tid;
            s_bias[tid] = (c < CACT) ? bn[c] : bt[c - CACT];
        }

        uint32_t* BH32 = (uint32_t*)(smc + B_HI);
        uint32_t* BL32 = (uint32_t*)(smc + B_LO);

        // ---- fold B half: 48 cols x 128 k-pairs, [n][kp] packed u32 ----
        {
            const float2* E2 = (const float2*)E;
#pragma unroll
            for (int it = 0; it < 24; ++it) {
                int i = tid + 256 * it;
                int c = i >> 7, kp = i & 127;
                int cg = half * 48 + c;
                const float2* wrow = (cg < CACT) ? (const float2*)(Wn + cg * Ddim)
                                                 : (const float2*)(Wt + (cg - CACT) * Ddim);
                int erow = (cg < CACT) ? (4 + cg) : (68 + (cg - CACT));
                float sc = (cg < CACT) ? s_ta : s_tt;
                float2 wv = wrow[kp];
                float2 ev = E2[erow * 128 + kp];
                float x0 = fmaf(sc, ev.x, wv.x), x1 = fmaf(sc, ev.y, wv.y);
                uint32_t hi, lo;
                hilo2(x0, x1, hi, lo);
                BH32[c * 132 + kp] = hi;
                BL32[c * 132 + kp] = lo;
            }
        }

        float acc[6][4];
#pragma unroll
        for (int j = 0; j < 6; ++j)
#pragma unroll
            for (int i = 0; i < 4; ++i) acc[j][i] = 0.f;

        uint32_t smem_base = smem_u32(smc);
        const float4* gh4 = (const float4*)h;
        int rt = wid;
        int a_row = rt * 16 + (lane & 15);
        int a_half = lane >> 4;

        // prologue: prefetch quarter 0
        float4 pv0[4], pv1[4];
#pragma unroll
        for (int it = 0; it < 4; ++it) {
            int i = tid + 256 * it;
            int r = i >> 3, c = i & 7;
            pv0[it] = gh4[(rowbase + r) * 64 + 2 * c];
            pv1[it] = gh4[(rowbase + r) * 64 + 2 * c + 1];
        }

        for (int q = 0; q < 4; ++q) {
            __syncthreads();   // previous quarter's A reads complete
#pragma unroll
            for (int it = 0; it < 4; ++it) {
                int i = tid + 256 * it;
                int r = i >> 3, c = i & 7;
                uint4 hi4, lo4;
                hilo2(pv0[it].x, pv0[it].y, hi4.x, lo4.x);
                hilo2(pv0[it].z, pv0[it].w, hi4.y, lo4.y);
                hilo2(pv1[it].x, pv1[it].y, hi4.z, lo4.z);
                hilo2(pv1[it].z, pv1[it].w, hi4.w, lo4.w);
                int sw = (c ^ (r & 7)) * 16;
                *(uint4*)(smc + A_HI + r * 128 + sw) = hi4;
                *(uint4*)(smc + A_LO + r * 128 + sw) = lo4;
            }
            if (q < 3) {
#pragma unroll
                for (int it = 0; it < 4; ++it) {
                    int i = tid + 256 * it;
                    int r = i >> 3, c = i & 7;
                    pv0[it] = gh4[(rowbase + r) * 64 + (q + 1) * 16 + 2 * c];
                    pv1[it] = gh4[(rowbase + r) * 64 + (q + 1) * 16 + 2 * c + 1];
                }
            }
            __syncthreads();   // staging visible

#pragma unroll
            for (int kc = 0; kc < 4; ++kc) {
                int chunk = kc * 2 + a_half;
                uint32_t a_off = a_row * 128 + ((chunk ^ (a_row & 7)) * 16);
                uint32_t aH0, aH1, aH2, aH3, aL0, aL1, aL2, aL3;
                ldsm4(smem_base + A_HI + a_off, aH0, aH1, aH2, aH3);
                ldsm4(smem_base + A_LO + a_off, aL0, aL1, aL2, aL3);

                int kpb = q * 32 + kc * 8;
#pragma unroll
                for (int j = 0; j < 6; ++j) {
                    int idx0 = (j * 8 + (lane >> 2)) * 132 + kpb + (lane & 3);
                    uint32_t bh0 = BH32[idx0], bh1 = BH32[idx0 + 4];
                    uint32_t bl0 = BL32[idx0], bl1 = BL32[idx0 + 4];
                    mma16816(acc[j], aH0, aH1, aH2, aH3, bh0, bh1);
                    mma16816(acc[j], aH0, aH1, aH2, aH3, bl0, bl1);
                    mma16816(acc[j], aL0, aL1, aL2, aL3, bh0, bh1);
                }
            }
        }

        // ---- epilogue: stage 128 x 48 to ob (reuse B region), direct stores ----
        __syncthreads();
        float* ob = sm;
        {
            int r0 = rt * 16 + (lane >> 2);
            int cb = 2 * (lane & 3);
#pragma unroll
            for (int j = 0; j < 6; ++j) {
                int col = cb + 8 * j;
                ob[r0 * 52 + col]           = acc[j][0] + s_bias[col];
                ob[r0 * 52 + col + 1]       = acc[j][1] + s_bias[col + 1];
                ob[(r0 + 8) * 52 + col]     = acc[j][2] + s_bias[col];
                ob[(r0 + 8) * 52 + col + 1] = acc[j][3] + s_bias[col + 1];
            }
        }
        __syncthreads();

        if (half == 0) {
#pragma unroll
            for (int it = 0; it < 6; ++it) {
                int i = tid + 256 * it;
                int r = i / 12, q2 = i % 12;
                float4 v = *(float4*)(ob + r * 52 + 4 * q2);
                *(float4*)(out + (rowbase + r) * CACT + 4 * q2) = v;
            }
        } else {
#pragma unroll
            for (int it = 0; it < 2; ++it) {
                int i = tid + 256 * it;
                int r = i >> 2, q2 = i & 3;
                float4 v = *(float4*)(ob + r * 52 + 4 * q2);
                *(float4*)(out + (rowbase + r) * CACT + 48 + 4 * q2) = v;
            }
            float* outT = out + (long)NROWS * CACT;
#pragma unroll
            for (int it = 0; it < 4; ++it) {
                int i = tid + 256 * it;
                int r = i >> 3, q2 = i & 7;
                float4 v = *(float4*)(ob + r * 52 + 16 + 4 * q2);
                *(float4*)(outT + (rowbase + r) * CTIME + 4 * q2) = v;
            }
        }
    } else {
        // ============ proto role: fully parallel G/M closed form ============
        int pb = bx;
        int b = pb / 3, part = pb % 3;
        int clo = (part == 0) ? 4 : (part == 1) ? 36 : 68;
        int klo = (part == 2) ? 68 : 4;
        int khi = (part == 2) ? 100 : 68;
        int cbase = part * 32;

        float* Q   = sm + P_Q;
        float* Hn  = sm + P_HN;
        float* G   = sm + P_G;
        float* M   = sm + P_M;
        float* NUM = sm + P_SB;
        float* SIM = sm + P_N2;
        int* toks  = (int*)(sm + P_TOK);
        __shared__ int s_nev, s_first;
        __shared__ float s_n2[32];
        __shared__ int CL[CHUNK], TE[CHUNK];

        for (int i = tid; i < Tdim; i += 256) toks[i] = tokens[(long)b * Tdim + i];
        __syncthreads();

        float alpha = softplusf(part == 2 ? *ppt : *ppa);
        float scale = softplusf(part == 2 ? *pst : *psa) * softplusf(part == 2 ? *ptt : *pta);

        if (wid == 0) {
            int cnt = 0, first = 0x7fffffff;
            for (int ch = 0; ch < Tdim / 32; ++ch) {
                int t = ch * 32 + lane;
                bool isl = (toks[t] == LABEL_ID_);
                unsigned m = __ballot_sync(0xffffffffu, isl);
                int ntok = isl ? toks[(t + 1) & (Tdim - 1)] : 0;
                if (isl) {
                    int idx = cnt + __popc(m & ((1u << lane) - 1u));
                    g_evt[pb * Tdim + idx] = t;
                    g_evn[pb * Tdim + idx] = ntok;
                }
                unsigned m2 = __ballot_sync(0xffffffffu, isl && ntok >= klo && ntok < khi);
                if (lane == 0 && m2 && first == 0x7fffffff) {
                    int l2 = __ffs(m2) - 1;
                    first = cnt + __popc(m & ((1u << l2) - 1u));
                }
                cnt += __popc(m);
            }
            if (lane == 0) { s_nev = cnt; s_first = first; g_nevd[pb] = cnt; }
        } else {
            for (int c = wid - 1; c < 32; c += 7) {
                const float* e = E + (long)(clo + c) * Ddim;
                float v[8]; float ss = 0.f;
#pragma unroll
                for (int k = 0; k < 8; ++k) { v[k] = e[lane + 32 * k]; ss += v[k] * v[k]; }
#pragma unroll
                for (int o = 16; o > 0; o >>= 1) ss += __shfl_xor_sync(0xffffffffu, ss, o);
                float inv = alpha / fmaxf(sqrtf(ss), 1e-12f);
#pragma unroll
                for (int k = 0; k < 8; ++k) Q[c * 260 + lane + 32 * k] = v[k] * inv;
            }
            if (wid == 1 && lane < 32) s_n2[lane] = alpha * alpha;
        }
        __syncthreads();

        int nev = s_nev, first_sup = s_first;
        const float* hb = h + (long)b * Tdim * Ddim;

        for (int c0 = 0; c0 < nev; c0 += CHUNK) {
            int cl = min(CHUNK, nev - c0);

            if (tid < cl) {
                TE[tid] = g_evt[pb * Tdim + c0 + tid];
                CL[tid] = g_evn[pb * Tdim + c0 + tid] - clo;
            }
            __syncthreads();
            for (int r = wid; r < cl; r += 8) {
                const float* hr = hb + (long)TE[r] * Ddim;
                float v[8]; float ss = 0.f;
#pragma unroll
                for (int k = 0; k < 8; ++k) { v[k] = hr[lane + 32 * k]; ss += v[k] * v[k]; }
#pragma unroll
                for (int o = 16; o > 0; o >>= 1) ss += __shfl_xor_sync(0xffffffffu, ss, o);
                float inv = 1.0f / fmaxf(sqrtf(ss), 1e-12f);
#pragma unroll
                for (int k = 0; k < 8; ++k) Hn[r * 260 + lane + 32 * k] = v[k] * inv;
            }
            __syncthreads();

            int cc = tid >> 3, seg = tid & 7;
            {
                float qv[32];
#pragma unroll
                for (int k = 0; k < 32; ++k)
                    qv[k] = Q[cc * 260 + seg * 32 + ((k + 4 * seg) & 31)];
                for (int e = 0; e < cl; ++e) {
                    const float* he = Hn + e * 260 + seg * 32;
                    float p0 = 0.f, p1 = 0.f, p2 = 0.f, p3 = 0.f;
#pragma unroll
                    for (int k = 0; k < 32; k += 4) {
                        p0 += qv[k]     * he[(k + 4 * seg) & 31];
                        p1 += qv[k + 1] * he[(k + 1 + 4 * seg) & 31];
                        p2 += qv[k + 2] * he[(k + 2 + 4 * seg) & 31];
                        p3 += qv[k + 3] * he[(k + 3 + 4 * seg) & 31];
                    }
                    float s1 = (p0 + p1) + (p2 + p3);
                    s1 += __shfl_xor_sync(0xffffffffu, s1, 4);
                    s1 += __shfl_xor_sync(0xffffffffu, s1, 2);
                    s1 += __shfl_xor_sync(0xffffffffu, s1, 1);
                    if (seg == 0) M[e * 32 + cc] = s1;
                }
            }
            {
                float hv[32];
#pragma unroll
                for (int k = 0; k < 32; ++k)
                    hv[k] = (cc < cl) ? Hn[cc * 260 + seg * 32 + ((k + 4 * seg) & 31)] : 0.f;
                for (int e = 0; e < cl; ++e) {
                    const float* he = Hn + e * 260 + seg * 32;
                    float p0 = 0.f, p1 = 0.f, p2 = 0.f, p3 = 0.f;
#pragma unroll
                    for (int k = 0; k < 32; k += 4) {
                        p0 += hv[k]     * he[(k + 4 * seg) & 31];
                        p1 += hv[k + 1] * he[(k + 1 + 4 * seg) & 31];
                        p2 += hv[k + 2] * he[(k + 2 + 4 * seg) & 31];
                        p3 += hv[k + 3] * he[(k + 3 + 4 * seg) & 31];
                    }
                    float s1 = (p0 + p1) + (p2 + p3);
                    s1 += __shfl_xor_sync(0xffffffffu, s1, 4);
                    s1 += __shfl_xor_sync(0xffffffffu, s1, 2);
                    s1 += __shfl_xor_sync(0xffffffffu, s1, 1);
                    if (seg == 0 && cc < cl) G[e * 32 + cc] = s1;
                }
            }
            __syncthreads();

            for (int idx = tid; idx < cl * 32; idx += 256) {
                int e = idx >> 5, c = idx & 31;
                float num = M[e * 32 + c];
                for (int e2 = 0; e2 < e; ++e2)
                    if (CL[e2] == c) num += G[e * 32 + e2];
                NUM[e * 32 + c] = num;
            }
            __syncthreads();
            for (int idx = tid; idx < cl * 32; idx += 256) {
                int e = idx >> 5, c = idx & 31;
                float n2 = s_n2[c];
                for (int e2 = 0; e2 < e; ++e2)
                    if (CL[e2] == c) n2 += 2.f * NUM[e2 * 32 + c] + G[e2 * 32 + e2];
                float num = NUM[e * 32 + c];
                SIM[e * 32 + c] = (c0 + e > first_sup) ? scale * num * rsqrtf(n2) : 0.f;
            }
            __syncthreads();

            for (int idx = tid; idx < cl * 32; idx += 256) {
                int e = idx >> 5, c = idx & 31;
                g_scr[((long)b * Tdim + TE[e]) * 96 + cbase + c] = SIM[e * 32 + c];
            }
            if (c0 + CHUNK < nev) {
                if (tid < 32) {
                    int c = tid;
                    float n2 = s_n2[c];
                    for (int e = 0; e < cl; ++e)
                        if (CL[e] == c) n2 += 2.f * NUM[e * 32 + c] + G[e * 32 + e];
                    s_n2[c] = n2;
                }
                __syncthreads();
                for (int e = 0; e < cl; ++e) {
                    int c2 = CL[e];
                    if (c2 >= 0 && c2 < 32)
                        Q[c2 * 260 + tid] += Hn[e * 260 + tid];
                }
                __syncthreads();
            }
        }
    }
}

// ---------------------------------------------------------------------------
// Epilogue: event-list driven, <=1 event per block, coalesced 96-wide add.
// ---------------------------------------------------------------------------
__global__ void __launch_bounds__(96) epi_kernel(float* __restrict__ out)
{
    int b = blockIdx.x >> 5, sub = blockIdx.x & 31;
    int c = threadIdx.x;
    int nev = g_nevd[b * 3];
    float* outT = out + (long)NROWS * CACT;
    for (int e = sub; e < nev; e += 32) {
        long row = (long)b * Tdim + g_evt[(b * 3) * Tdim + e];
        float v = g_scr[row * 96 + c];
        if (c < CACT) out[row * CACT + c] += v;
        else          outT[row * CTIME + (c - CACT)] += v;
    }
}

extern "C" void kernel_launch(void* const* d_in, const int* in_sizes, int n_in,
                              void* d_out, int out_size)
{
    cudaFuncSetAttribute(fat_kernel, cudaFuncAttributeMaxDynamicSharedMemorySize, SMEM_BYTES);

    fat_kernel<<<24 + 256, 256, SMEM_BYTES>>>(
        (const int*)d_in[0], (const float*)d_in[1], (const float*)d_in[2],
        (const float*)d_in[3], (const float*)d_in[4],
        (const float*)d_in[5], (const float*)d_in[6],
        (const float*)d_in[7], (const float*)d_in[8],
        (const float*)d_in[9], (const float*)d_in[10],
        (const float*)d_in[11], (const float*)d_in[12],
        (const float*)d_in[13], (const float*)d_in[14],
        (float*)d_out);

    epi_kernel<<<256, 96>>>((float*)d_out);
}

// round 16
// speedup vs baseline: 1.5861x; 1.0009x over previous
#include <cuda_runtime.h>
#include <math.h>
#include <stdint.h>

#define Tdim 2048
#define Ddim 256
#define CACT 64
#define CTIME 32
#define NROWS (8 * 2048)
#define LABEL_ID_ 3
#define CHUNK 32

// ---- gemm smem (byte offsets), block = 128 rows x 48 cols ----
#define B_HI 0                    // 48 x 132 u32 (packed bf16 k-pairs)
#define B_LO 25344
#define A_HI 50688                // 128 rows x 128B (one K-quarter)
#define A_LO 67072                // -> 83456
// ---- proto smem (float offsets) ----
#define P_Q   0                   // 32 x 260
#define P_HN  8320                // 32 x 260
#define P_G   16640               // 32 x 32
#define P_M   17664               // 32 x 32
#define P_SB  18688               // 32 x 32 (num)
#define P_N2  19712               // 32 x 32 (sims out)
#define P_TOK 20736               // 2048 ints
#define SMEM_BYTES 91136

__device__ float g_scr[(long)NROWS * 96];
__device__ int   g_evt[24 * Tdim];
__device__ int   g_evn[24 * Tdim];
__device__ int   g_done[8];

__device__ __forceinline__ float softplusf(float x) { return log1pf(expf(x)); }

__device__ __forceinline__ uint32_t smem_u32(const void* p) {
    uint32_t a;
    asm("{ .reg .u64 t; cvta.to.shared.u64 t, %1; cvt.u32.u64 %0, t; }" : "=r"(a) : "l"(p));
    return a;
}
__device__ __forceinline__ void hilo2(float x0, float x1, uint32_t& hi, uint32_t& lo) {
    asm("cvt.rn.bf16x2.f32 %0, %1, %2;" : "=r"(hi) : "f"(x1), "f"(x0));
    float h0 = __uint_as_float(hi << 16);
    float h1 = __uint_as_float(hi & 0xffff0000u);
    asm("cvt.rn.bf16x2.f32 %0, %1, %2;" : "=r"(lo) : "f"(x1 - h1), "f"(x0 - h0));
}
__device__ __forceinline__ void ldsm4(uint32_t addr, uint32_t& r0, uint32_t& r1,
                                      uint32_t& r2, uint32_t& r3) {
    asm volatile("ldmatrix.sync.aligned.m8n8.x4.shared.b16 {%0,%1,%2,%3}, [%4];"
                 : "=r"(r0), "=r"(r1), "=r"(r2), "=r"(r3) : "r"(addr));
}
__device__ __forceinline__ void mma16816(float* c, uint32_t a0, uint32_t a1,
                                         uint32_t a2, uint32_t a3,
                                         uint32_t b0, uint32_t b1) {
    asm volatile(
        "mma.sync.aligned.m16n8k16.row.col.f32.bf16.bf16.f32 "
        "{%0,%1,%2,%3},{%4,%5,%6,%7},{%8,%9},{%0,%1,%2,%3};"
        : "+f"(c[0]), "+f"(c[1]), "+f"(c[2]), "+f"(c[3])
        : "r"(a0), "r"(a1), "r"(a2), "r"(a3), "r"(b0), "r"(b1));
}

__global__ void reset_kernel() {
    if (threadIdx.x < 8) g_done[threadIdx.x] = 0;
}

__global__ void __launch_bounds__(256, 2) fat_kernel(
    const int* __restrict__ tokens, const float* __restrict__ h,
    const float* __restrict__ E,
    const float* __restrict__ Wn, const float* __restrict__ bn,
    const float* __restrict__ Wt, const float* __restrict__ bt,
    const float* __restrict__ tsa, const float* __restrict__ tst,
    const float* __restrict__ psa, const float* __restrict__ pst,
    const float* __restrict__ ppa, const float* __restrict__ ppt,
    const float* __restrict__ pta, const float* __restrict__ ptt,
    float* __restrict__ out)
{
    extern __shared__ char smc[];
    float* sm = (float*)smc;
    int tid = threadIdx.x, lane = tid & 31, wid = tid >> 5;
    int bx = blockIdx.x;

    if (bx >= 24) {
        // ============ GEMM role: fully decoupled, direct stores, publishes done flag ============
        __shared__ float s_bias[48];

        int g = bx - 24;
        int half = g & 1;
        long rowbase = (long)(g >> 1) * 128;
        int b = (int)(rowbase >> 11);
        float s_ta = softplusf(*tsa), s_tt = softplusf(*tst);

        if (tid < 48) {
            int c = half * 48 + tid;
            s_bias[tid] = (c < CACT) ? bn[c] : bt[c - CACT];
        }

        uint32_t* BH32 = (uint32_t*)(smc + B_HI);
        uint32_t* BL32 = (uint32_t*)(smc + B_LO);
        const float4* gh4 = (const float4*)h;

        // prologue: prefetch A quarter 0 FIRST (DRAM latency overlaps B fold)
        float4 pv0[4], pv1[4];
#pragma unroll
        for (int it = 0; it < 4; ++it) {
            int i = tid + 256 * it;
            int r = i >> 3, c = i & 7;
            pv0[it] = gh4[(rowbase + r) * 64 + 2 * c];
            pv1[it] = gh4[(rowbase + r) * 64 + 2 * c + 1];
        }

        // ---- fold B half: 48 cols x 128 k-pairs, [n][kp] packed u32 ----
        {
            const float2* E2 = (const float2*)E;
#pragma unroll
            for (int it = 0; it < 24; ++it) {
                int i = tid + 256 * it;
                int c = i >> 7, kp = i & 127;
                int cg = half * 48 + c;
                const float2* wrow = (cg < CACT) ? (const float2*)(Wn + cg * Ddim)
                                                 : (const float2*)(Wt + (cg - CACT) * Ddim);
                int erow = (cg < CACT) ? (4 + cg) : (68 + (cg - CACT));
                float sc = (cg < CACT) ? s_ta : s_tt;
                float2 wv = wrow[kp];
                float2 ev = E2[erow * 128 + kp];
                float x0 = fmaf(sc, ev.x, wv.x), x1 = fmaf(sc, ev.y, wv.y);
                uint32_t hi, lo;
                hilo2(x0, x1, hi, lo);
                BH32[c * 132 + kp] = hi;
                BL32[c * 132 + kp] = lo;
            }
        }

        float acc[6][4];
#pragma unroll
        for (int j = 0; j < 6; ++j)
#pragma unroll
            for (int i = 0; i < 4; ++i) acc[j][i] = 0.f;

        uint32_t smem_base = smem_u32(smc);
        int rt = wid;
        int a_row = rt * 16 + (lane & 15);
        int a_half = lane >> 4;

        for (int q = 0; q < 4; ++q) {
            __syncthreads();   // previous quarter's A reads complete
#pragma unroll
            for (int it = 0; it < 4; ++it) {
                int i = tid + 256 * it;
                int r = i >> 3, c = i & 7;
                uint4 hi4, lo4;
                hilo2(pv0[it].x, pv0[it].y, hi4.x, lo4.x);
                hilo2(pv0[it].z, pv0[it].w, hi4.y, lo4.y);
                hilo2(pv1[it].x, pv1[it].y, hi4.z, lo4.z);
                hilo2(pv1[it].z, pv1[it].w, hi4.w, lo4.w);
                int sw = (c ^ (r & 7)) * 16;
                *(uint4*)(smc + A_HI + r * 128 + sw) = hi4;
                *(uint4*)(smc + A_LO + r * 128 + sw) = lo4;
            }
            if (q < 3) {
#pragma unroll
                for (int it = 0; it < 4; ++it) {
                    int i = tid + 256 * it;
                    int r = i >> 3, c = i & 7;
                    pv0[it] = gh4[(rowbase + r) * 64 + (q + 1) * 16 + 2 * c];
                    pv1[it] = gh4[(rowbase + r) * 64 + (q + 1) * 16 + 2 * c + 1];
                }
            }
            __syncthreads();   // staging visible

#pragma unroll
            for (int kc = 0; kc < 4; ++kc) {
                int chunk = kc * 2 + a_half;
                uint32_t a_off = a_row * 128 + ((chunk ^ (a_row & 7)) * 16);
                uint32_t aH0, aH1, aH2, aH3, aL0, aL1, aL2, aL3;
                ldsm4(smem_base + A_HI + a_off, aH0, aH1, aH2, aH3);
                ldsm4(smem_base + A_LO + a_off, aL0, aL1, aL2, aL3);

                int kpb = q * 32 + kc * 8;
#pragma unroll
                for (int j = 0; j < 6; ++j) {
                    int idx0 = (j * 8 + (lane >> 2)) * 132 + kpb + (lane & 3);
                    uint32_t bh0 = BH32[idx0], bh1 = BH32[idx0 + 4];
                    uint32_t bl0 = BL32[idx0], bl1 = BL32[idx0 + 4];
                    mma16816(acc[j], aH0, aH1, aH2, aH3, bh0, bh1);
                    mma16816(acc[j], aH0, aH1, aH2, aH3, bl0, bl1);
                    mma16816(acc[j], aL0, aL1, aL2, aL3, bh0, bh1);
                }
            }
        }

        // ---- epilogue: stage 128 x 48 to ob (reuse B region), direct stores ----
        __syncthreads();
        float* ob = sm;
        {
            int r0 = rt * 16 + (lane >> 2);
            int cb = 2 * (lane & 3);
#pragma unroll
            for (int j = 0; j < 6; ++j) {
                int col = cb + 8 * j;
                ob[r0 * 52 + col]           = acc[j][0] + s_bias[col];
                ob[r0 * 52 + col + 1]       = acc[j][1] + s_bias[col + 1];
                ob[(r0 + 8) * 52 + col]     = acc[j][2] + s_bias[col];
                ob[(r0 + 8) * 52 + col + 1] = acc[j][3] + s_bias[col + 1];
            }
        }
        __syncthreads();

        if (half == 0) {
#pragma unroll
            for (int it = 0; it < 6; ++it) {
                int i = tid + 256 * it;
                int r = i / 12, q2 = i % 12;
                float4 v = *(float4*)(ob + r * 52 + 4 * q2);
                *(float4*)(out + (rowbase + r) * CACT + 4 * q2) = v;
            }
        } else {
#pragma unroll
            for (int it = 0; it < 2; ++it) {
                int i = tid + 256 * it;
                int r = i >> 2, q2 = i & 3;
                float4 v = *(float4*)(ob + r * 52 + 4 * q2);
                *(float4*)(out + (rowbase + r) * CACT + 48 + 4 * q2) = v;
            }
            float* outT = out + (long)NROWS * CACT;
#pragma unroll
            for (int it = 0; it < 4; ++it) {
                int i = tid + 256 * it;
                int r = i >> 3, q2 = i & 7;
                float4 v = *(float4*)(ob + r * 52 + 16 + 4 * q2);
                *(float4*)(outT + (rowbase + r) * CTIME + 4 * q2) = v;
            }
        }
        // publish: this tile-half's rows are final (modulo proto add)
        __syncthreads();
        if (tid == 0) {
            __threadfence();
            atomicAdd(&g_done[b], 1);
        }
    } else {
        // ============ proto role: parallel G/M sims, then merge into out ============
        int pb = bx;
        int b = pb / 3, part = pb % 3;
        int clo = (part == 0) ? 4 : (part == 1) ? 36 : 68;
        int klo = (part == 2) ? 68 : 4;
        int khi = (part == 2) ? 100 : 68;
        int cbase = part * 32;

        float* Q   = sm + P_Q;
        float* Hn  = sm + P_HN;
        float* G   = sm + P_G;
        float* M   = sm + P_M;
        float* NUM = sm + P_SB;
        float* SIM = sm + P_N2;
        int* toks  = (int*)(sm + P_TOK);
        __shared__ int s_nev, s_first;
        __shared__ float s_n2[32];
        __shared__ int CL[CHUNK], TE[CHUNK];

        for (int i = tid; i < Tdim; i += 256) toks[i] = tokens[(long)b * Tdim + i];
        __syncthreads();

        float alpha = softplusf(part == 2 ? *ppt : *ppa);
        float scale = softplusf(part == 2 ? *pst : *psa) * softplusf(part == 2 ? *ptt : *pta);

        if (wid == 0) {
            int cnt = 0, first = 0x7fffffff;
            for (int ch = 0; ch < Tdim / 32; ++ch) {
                int t = ch * 32 + lane;
                bool isl = (toks[t] == LABEL_ID_);
                unsigned m = __ballot_sync(0xffffffffu, isl);
                int ntok = isl ? toks[(t + 1) & (Tdim - 1)] : 0;
                if (isl) {
                    int idx = cnt + __popc(m & ((1u << lane) - 1u));
                    g_evt[pb * Tdim + idx] = t;
                    g_evn[pb * Tdim + idx] = ntok;
                }
                unsigned m2 = __ballot_sync(0xffffffffu, isl && ntok >= klo && ntok < khi);
                if (lane == 0 && m2 && first == 0x7fffffff) {
                    int l2 = __ffs(m2) - 1;
                    first = cnt + __popc(m & ((1u << l2) - 1u));
                }
                cnt += __popc(m);
            }
            if (lane == 0) { s_nev = cnt; s_first = first; }
        } else {
            for (int c = wid - 1; c < 32; c += 7) {
                const float* e = E + (long)(clo + c) * Ddim;
                float v[8]; float ss = 0.f;
#pragma unroll
                for (int k = 0; k < 8; ++k) { v[k] = e[lane + 32 * k]; ss += v[k] * v[k]; }
#pragma unroll
                for (int o = 16; o > 0; o >>= 1) ss += __shfl_xor_sync(0xffffffffu, ss, o);
                float inv = alpha / fmaxf(sqrtf(ss), 1e-12f);
#pragma unroll
                for (int k = 0; k < 8; ++k) Q[c * 260 + lane + 32 * k] = v[k] * inv;
            }
            if (wid == 1 && lane < 32) s_n2[lane] = alpha * alpha;
        }
        __syncthreads();

        int nev = s_nev, first_sup = s_first;
        const float* hb = h + (long)b * Tdim * Ddim;

        for (int c0 = 0; c0 < nev; c0 += CHUNK) {
            int cl = min(CHUNK, nev - c0);

            if (tid < cl) {
                TE[tid] = g_evt[pb * Tdim + c0 + tid];
                CL[tid] = g_evn[pb * Tdim + c0 + tid] - clo;
            }
            __syncthreads();
            for (int r = wid; r < cl; r += 8) {
                const float* hr = hb + (long)TE[r] * Ddim;
                float v[8]; float ss = 0.f;
#pragma unroll
                for (int k = 0; k < 8; ++k) { v[k] = hr[lane + 32 * k]; ss += v[k] * v[k]; }
#pragma unroll
                for (int o = 16; o > 0; o >>= 1) ss += __shfl_xor_sync(0xffffffffu, ss, o);
                float inv = 1.0f / fmaxf(sqrtf(ss), 1e-12f);
#pragma unroll
                for (int k = 0; k < 8; ++k) Hn[r * 260 + lane + 32 * k] = v[k] * inv;
            }
            __syncthreads();

            int cc = tid >> 3, seg = tid & 7;
            {
                float qv[32];
#pragma unroll
                for (int k = 0; k < 32; ++k)
                    qv[k] = Q[cc * 260 + seg * 32 + ((k + 4 * seg) & 31)];
                for (int e = 0; e < cl; ++e) {
                    const float* he = Hn + e * 260 + seg * 32;
                    float p0 = 0.f, p1 = 0.f, p2 = 0.f, p3 = 0.f;
#pragma unroll
                    for (int k = 0; k < 32; k += 4) {
                        p0 += qv[k]     * he[(k + 4 * seg) & 31];
                        p1 += qv[k + 1] * he[(k + 1 + 4 * seg) & 31];
                        p2 += qv[k + 2] * he[(k + 2 + 4 * seg) & 31];
                        p3 += qv[k + 3] * he[(k + 3 + 4 * seg) & 31];
                    }
                    float s1 = (p0 + p1) + (p2 + p3);
                    s1 += __shfl_xor_sync(0xffffffffu, s1, 4);
                    s1 += __shfl_xor_sync(0xffffffffu, s1, 2);
                    s1 += __shfl_xor_sync(0xffffffffu, s1, 1);
                    if (seg == 0) M[e * 32 + cc] = s1;
                }
            }
            {
                float hv[32];
#pragma unroll
                for (int k = 0; k < 32; ++k)
                    hv[k] = (cc < cl) ? Hn[cc * 260 + seg * 32 + ((k + 4 * seg) & 31)] : 0.f;
                for (int e = 0; e < cl; ++e) {
                    const float* he = Hn + e * 260 + seg * 32;
                    float p0 = 0.f, p1 = 0.f, p2 = 0.f, p3 = 0.f;
#pragma unroll
                    for (int k = 0; k < 32; k += 4) {
                        p0 += hv[k]     * he[(k + 4 * seg) & 31];
                        p1 += hv[k + 1] * he[(k + 1 + 4 * seg) & 31];
                        p2 += hv[k + 2] * he[(k + 2 + 4 * seg) & 31];
                        p3 += hv[k + 3] * he[(k + 3 + 4 * seg) & 31];
                    }
                    float s1 = (p0 + p1) + (p2 + p3);
                    s1 += __shfl_xor_sync(0xffffffffu, s1, 4);
                    s1 += __shfl_xor_sync(0xffffffffu, s1, 2);
                    s1 += __shfl_xor_sync(0xffffffffu, s1, 1);
                    if (seg == 0 && cc < cl) G[e * 32 + cc] = s1;
                }
            }
            __syncthreads();

            for (int idx = tid; idx < cl * 32; idx += 256) {
                int e = idx >> 5, c = idx & 31;
                float num = M[e * 32 + c];
                for (int e2 = 0; e2 < e; ++e2)
                    if (CL[e2] == c) num += G[e * 32 + e2];
                NUM[e * 32 + c] = num;
            }
            __syncthreads();
            for (int idx = tid; idx < cl * 32; idx += 256) {
                int e = idx >> 5, c = idx & 31;
                float n2 = s_n2[c];
                for (int e2 = 0; e2 < e; ++e2)
                    if (CL[e2] == c) n2 += 2.f * NUM[e2 * 32 + c] + G[e2 * 32 + e2];
                float num = NUM[e * 32 + c];
                SIM[e * 32 + c] = (c0 + e > first_sup) ? scale * num * rsqrtf(n2) : 0.f;
            }
            __syncthreads();

            for (int idx = tid; idx < cl * 32; idx += 256) {
                int e = idx >> 5, c = idx & 31;
                g_scr[((long)b * Tdim + TE[e]) * 96 + cbase + c] = SIM[e * 32 + c];
            }
            if (c0 + CHUNK < nev) {
                if (tid < 32) {
                    int c = tid;
                    float n2 = s_n2[c];
                    for (int e = 0; e < cl; ++e)
                        if (CL[e] == c) n2 += 2.f * NUM[e * 32 + c] + G[e * 32 + e];
                    s_n2[c] = n2;
                }
                __syncthreads();
                for (int e = 0; e < cl; ++e) {
                    int c2 = CL[e];
                    if (c2 >= 0 && c2 < 32)
                        Q[c2 * 260 + tid] += Hn[e * 260 + tid];
                }
                __syncthreads();
            }
        }

        // ---- merge: wait for this batch's 32 gemm blocks, then add our slice ----
        __threadfence();   // sims in g_scr visible before we start reading out
        if (tid == 0) {
            while (*(volatile int*)&g_done[b] < 32) __nanosleep(64);
            __threadfence();
        }
        __syncthreads();

        float* outT = out + (long)NROWS * CACT;
        for (int e = tid >> 5; e < nev; e += 8) {
            long row = (long)b * Tdim + g_evt[pb * Tdim + e];
            int c = lane;
            float v = __ldcg(&g_scr[row * 96 + cbase + c]);
            if (part < 2) out[row * CACT + cbase + c] += v;
            else          outT[row * CTIME + c] += v;
        }
    }
}

extern "C" void kernel_launch(void* const* d_in, const int* in_sizes, int n_in,
                              void* d_out, int out_size)
{
    cudaFuncSetAttribute(fat_kernel, cudaFuncAttributeMaxDynamicSharedMemorySize, SMEM_BYTES);

    reset_kernel<<<1, 32>>>();

    fat_kernel<<<24 + 256, 256, SMEM_BYTES>>>(
        (const int*)d_in[0], (const float*)d_in[1], (const float*)d_in[2],
        (const float*)d_in[3], (const float*)d_in[4],
        (const float*)d_in[5], (const float*)d_in[6],
        (const float*)d_in[7], (const float*)d_in[8],
        (const float*)d_in[9], (const float*)d_in[10],
        (const float*)d_in[11], (const float*)d_in[12],
        (const float*)d_in[13], (const float*)d_in[14],
        (float*)d_out);
}